// round 1
// baseline (speedup 1.0000x reference)
#include <cuda_runtime.h>
#include <cuda_bf16.h>

// Problem constants
#define BB 4
#define TT 2048
#define HH 1024
#define NH 16
#define HD 64
#define ROWS (BB*TT)          // 8192
#define QKV_COLS (3*HH)       // 3072

// Scratch (device globals; no runtime allocation allowed)
__device__ float g_qkv[(size_t)ROWS * QKV_COLS];   // [B*T, 3H]
__device__ float g_attn[(size_t)ROWS * HH];        // [B*T, H]

// ---------------------------------------------------------------------------
// GEMM (NT): C[M,N] = A[M,K] * B[N,K]^T   (A row-major, B row-major [N,K])
// 128x128 block tile, BK=16, 256 threads, 8x8 per-thread microtile.
// All dims are multiples of tile sizes for this problem -> no bounds checks.
// ---------------------------------------------------------------------------
__global__ __launch_bounds__(256) void gemm_nt(const float* __restrict__ A,
                                               const float* __restrict__ Bm,
                                               float* __restrict__ C,
                                               int M, int N, int K) {
    __shared__ float As[16][128];
    __shared__ float Bs[16][128];

    const int tid = threadIdx.x;
    const int tx = tid & 15;          // 0..15
    const int ty = tid >> 4;          // 0..15
    const int m0 = blockIdx.y * 128;
    const int n0 = blockIdx.x * 128;

    const int lr = tid >> 2;          // 0..63 (row within tile)
    const int lc = (tid & 3) * 4;     // k offset: 0,4,8,12

    const float* Ap0 = A + (size_t)(m0 + lr) * K + lc;
    const float* Ap1 = A + (size_t)(m0 + lr + 64) * K + lc;
    const float* Bp0 = Bm + (size_t)(n0 + lr) * K + lc;
    const float* Bp1 = Bm + (size_t)(n0 + lr + 64) * K + lc;

    float acc[8][8] = {};

    for (int k0 = 0; k0 < K; k0 += 16) {
        float4 a0 = *(const float4*)(Ap0 + k0);
        float4 a1 = *(const float4*)(Ap1 + k0);
        float4 b0 = *(const float4*)(Bp0 + k0);
        float4 b1 = *(const float4*)(Bp1 + k0);

        __syncthreads();  // previous iteration's consumers done

        As[lc + 0][lr] = a0.x; As[lc + 1][lr] = a0.y;
        As[lc + 2][lr] = a0.z; As[lc + 3][lr] = a0.w;
        As[lc + 0][lr + 64] = a1.x; As[lc + 1][lr + 64] = a1.y;
        As[lc + 2][lr + 64] = a1.z; As[lc + 3][lr + 64] = a1.w;
        Bs[lc + 0][lr] = b0.x; Bs[lc + 1][lr] = b0.y;
        Bs[lc + 2][lr] = b0.z; Bs[lc + 3][lr] = b0.w;
        Bs[lc + 0][lr + 64] = b1.x; Bs[lc + 1][lr + 64] = b1.y;
        Bs[lc + 2][lr + 64] = b1.z; Bs[lc + 3][lr + 64] = b1.w;

        __syncthreads();

        #pragma unroll
        for (int kk = 0; kk < 16; kk++) {
            float af[8], bf[8];
            *(float4*)&af[0] = *(const float4*)&As[kk][ty * 8];
            *(float4*)&af[4] = *(const float4*)&As[kk][ty * 8 + 4];
            *(float4*)&bf[0] = *(const float4*)&Bs[kk][tx * 8];
            *(float4*)&bf[4] = *(const float4*)&Bs[kk][tx * 8 + 4];
            #pragma unroll
            for (int i = 0; i < 8; i++)
                #pragma unroll
                for (int j = 0; j < 8; j++)
                    acc[i][j] += af[i] * bf[j];
        }
    }

    #pragma unroll
    for (int i = 0; i < 8; i++) {
        float* cp = C + (size_t)(m0 + ty * 8 + i) * N + n0 + tx * 8;
        *(float4*)(cp + 0) = make_float4(acc[i][0], acc[i][1], acc[i][2], acc[i][3]);
        *(float4*)(cp + 4) = make_float4(acc[i][4], acc[i][5], acc[i][6], acc[i][7]);
    }
}

// ---------------------------------------------------------------------------
// Causal flash attention.
// One block = one (batch, head, q-tile of 64 rows). 256 threads.
// Online softmax; k-tiles of 32; only visits k-tiles <= causal boundary.
// qkv layout: [B*T, 3H], q at cols [h*64..), k at 1024+h*64, v at 2048+h*64.
// out: [B*T, H] at cols h*64.
// ---------------------------------------------------------------------------
__global__ __launch_bounds__(256) void flash_attn(const float* __restrict__ qkv,
                                                  float* __restrict__ out) {
    const int qt = blockIdx.x;
    const int h  = blockIdx.y;
    const int b  = blockIdx.z;
    const int tid = threadIdx.x;
    const int tx = tid & 15;   // 0..15
    const int ty = tid >> 4;   // 0..15

    __shared__ float Qt[64][68];    // Qt[d][r]  (transposed)
    __shared__ float Kt[64][36];    // Kt[d][c]  (transposed)
    __shared__ float Vs[32][68];    // Vs[c][d]
    __shared__ float Ssm[64][36];   // Ssm[r][c]
    __shared__ float rm[64], rl[64], rcorr[64];

    const int q0 = qt * 64;
    const size_t rstride = QKV_COLS;
    const float* qbase = qkv + ((size_t)b * TT + q0) * rstride + h * HD;

    // Load Q tile (64x64) transposed into Qt
    #pragma unroll
    for (int i = 0; i < 4; i++) {
        int fl = tid + i * 256;              // 0..1023
        int r  = fl >> 4;                    // 0..63
        int c4 = (fl & 15) * 4;              // 0..60
        float4 v = *(const float4*)(qbase + (size_t)r * rstride + c4);
        Qt[c4 + 0][r] = v.x; Qt[c4 + 1][r] = v.y;
        Qt[c4 + 2][r] = v.z; Qt[c4 + 3][r] = v.w;
    }
    if (tid < 64) { rm[tid] = -1e30f; rl[tid] = 0.0f; }

    float o[4][4] = {};
    const int nkt = 2 * qt + 2;

    for (int kt = 0; kt < nkt; kt++) {
        __syncthreads();   // smem safe to overwrite

        // Load K (32x64 -> transposed) and V (32x64)
        const float* kbase = qkv + ((size_t)b * TT + kt * 32) * rstride + HH + h * HD;
        const float* vbase = qkv + ((size_t)b * TT + kt * 32) * rstride + 2 * HH + h * HD;
        #pragma unroll
        for (int i = 0; i < 2; i++) {
            int fl = tid + i * 256;          // 0..511
            int r  = fl >> 4;                // 0..31
            int c4 = (fl & 15) * 4;
            float4 kv = *(const float4*)(kbase + (size_t)r * rstride + c4);
            Kt[c4 + 0][r] = kv.x; Kt[c4 + 1][r] = kv.y;
            Kt[c4 + 2][r] = kv.z; Kt[c4 + 3][r] = kv.w;
            float4 vv = *(const float4*)(vbase + (size_t)r * rstride + c4);
            *(float4*)&Vs[r][c4] = vv;
        }
        __syncthreads();

        // S = Q K^T  -> each thread 4 rows x 2 cols
        {
            float acc[4][2] = {};
            #pragma unroll 16
            for (int d = 0; d < 64; d++) {
                float4 qf = *(const float4*)&Qt[d][ty * 4];
                float2 kf = *(const float2*)&Kt[d][tx * 2];
                acc[0][0] += qf.x * kf.x; acc[0][1] += qf.x * kf.y;
                acc[1][0] += qf.y * kf.x; acc[1][1] += qf.y * kf.y;
                acc[2][0] += qf.z * kf.x; acc[2][1] += qf.z * kf.y;
                acc[3][0] += qf.w * kf.x; acc[3][1] += qf.w * kf.y;
            }
            #pragma unroll
            for (int i = 0; i < 4; i++) {
                int qg = q0 + ty * 4 + i;
                #pragma unroll
                for (int j = 0; j < 2; j++) {
                    int kg = kt * 32 + tx * 2 + j;
                    float s = acc[i][j] * 0.125f;     // 1/sqrt(64)
                    if (kg > qg) s = -1e9f;
                    Ssm[ty * 4 + i][tx * 2 + j] = s;
                }
            }
        }
        __syncthreads();

        // Online softmax: 4 threads per row, 8 cols each
        {
            int r = tid >> 2, sub = tid & 3;
            float* srow = &Ssm[r][sub * 8];
            float v[8];
            *(float4*)&v[0] = *(const float4*)&srow[0];
            *(float4*)&v[4] = *(const float4*)&srow[4];
            float vmax = v[0];
            #pragma unroll
            for (int j = 1; j < 8; j++) vmax = fmaxf(vmax, v[j]);
            vmax = fmaxf(vmax, __shfl_xor_sync(0xffffffffu, vmax, 1));
            vmax = fmaxf(vmax, __shfl_xor_sync(0xffffffffu, vmax, 2));
            float mold = rm[r];
            float mnew = fmaxf(mold, vmax);
            float sum = 0.0f;
            #pragma unroll
            for (int j = 0; j < 8; j++) {
                float p = __expf(v[j] - mnew);
                v[j] = p;
                sum += p;
            }
            *(float4*)&srow[0] = *(const float4*)&v[0];
            *(float4*)&srow[4] = *(const float4*)&v[4];
            sum += __shfl_xor_sync(0xffffffffu, sum, 1);
            sum += __shfl_xor_sync(0xffffffffu, sum, 2);
            float corr = __expf(mold - mnew);
            if (sub == 0) {
                rcorr[r] = corr;
                rl[r] = rl[r] * corr + sum;
                rm[r] = mnew;
            }
        }
        __syncthreads();

        // O = O*corr + P @ V   -> each thread 4 rows x 4 d-cols
        {
            #pragma unroll
            for (int i = 0; i < 4; i++) {
                float cf = rcorr[ty * 4 + i];
                o[i][0] *= cf; o[i][1] *= cf; o[i][2] *= cf; o[i][3] *= cf;
            }
            #pragma unroll 8
            for (int kk = 0; kk < 32; kk++) {
                float4 vf = *(const float4*)&Vs[kk][tx * 4];
                #pragma unroll
                for (int i = 0; i < 4; i++) {
                    float p = Ssm[ty * 4 + i][kk];
                    o[i][0] += p * vf.x;
                    o[i][1] += p * vf.y;
                    o[i][2] += p * vf.z;
                    o[i][3] += p * vf.w;
                }
            }
        }
    }

    // Normalize + write out
    float* obase = out + ((size_t)b * TT + q0) * HH + h * HD;
    #pragma unroll
    for (int i = 0; i < 4; i++) {
        float inv = 1.0f / rl[ty * 4 + i];
        *(float4*)(obase + (size_t)(ty * 4 + i) * HH + tx * 4) =
            make_float4(o[i][0] * inv, o[i][1] * inv, o[i][2] * inv, o[i][3] * inv);
    }
}

// ---------------------------------------------------------------------------
extern "C" void kernel_launch(void* const* d_in, const int* in_sizes, int n_in,
                              void* d_out, int out_size) {
    const float* x     = (const float*)d_in[0];   // [4,2048,1024]
    const float* Wqkv  = (const float*)d_in[1];   // [3072,1024]
    const float* Wout  = (const float*)d_in[2];   // [1024,1024]
    float* out = (float*)d_out;                   // [4,2048,1024]

    float* qkv = nullptr;
    float* attn = nullptr;
    cudaGetSymbolAddress((void**)&qkv, g_qkv);
    cudaGetSymbolAddress((void**)&attn, g_attn);

    // 1) qkv = x @ W_qkv^T : [8192,1024] x [3072,1024]^T -> [8192,3072]
    gemm_nt<<<dim3(QKV_COLS / 128, ROWS / 128), 256>>>(x, Wqkv, qkv, ROWS, QKV_COLS, HH);

    // 2) causal flash attention per (b, h, q-tile)
    flash_attn<<<dim3(TT / 64, NH, BB), 256>>>(qkv, attn);

    // 3) out = attn @ W_out^T : [8192,1024] x [1024,1024]^T -> [8192,1024]
    gemm_nt<<<dim3(HH / 128, ROWS / 128), 256>>>(attn, Wout, out, ROWS, HH, HH);
}

// round 3
// speedup vs baseline: 1.4914x; 1.4914x over previous
#include <cuda_runtime.h>
#include <cuda_bf16.h>
#include <cstdint>

// Problem constants
#define BB 4
#define TT 2048
#define HH 1024
#define NH 16
#define HD 64
#define ROWS (BB*TT)          // 8192
#define QKV_COLS (3*HH)       // 3072

// Scratch (device globals; no runtime allocation allowed)
__device__ float g_qkv[(size_t)ROWS * QKV_COLS];          // [B*T, 3H] fp32
__device__ __nv_bfloat16 g_x_hi[(size_t)ROWS * HH];
__device__ __nv_bfloat16 g_x_lo[(size_t)ROWS * HH];
__device__ __nv_bfloat16 g_wqkv_hi[(size_t)QKV_COLS * HH];
__device__ __nv_bfloat16 g_wqkv_lo[(size_t)QKV_COLS * HH];
__device__ __nv_bfloat16 g_wout_hi[(size_t)HH * HH];
__device__ __nv_bfloat16 g_wout_lo[(size_t)HH * HH];
__device__ __nv_bfloat16 g_attn_hi[(size_t)ROWS * HH];
__device__ __nv_bfloat16 g_attn_lo[(size_t)ROWS * HH];

// ---------------------------------------------------------------------------
// Helpers
// ---------------------------------------------------------------------------
__device__ __forceinline__ uint32_t smem_u32_of(const void* p) {
    uint32_t a;
    asm("{ .reg .u64 t; cvta.to.shared.u64 t, %1; cvt.u32.u64 %0, t; }"
        : "=r"(a) : "l"(p));
    return a;
}

#define CPA16(dst, src) \
    asm volatile("cp.async.cg.shared.global [%0], [%1], 16;" :: "r"(dst), "l"(src))
#define CPA_COMMIT() asm volatile("cp.async.commit_group;" ::: "memory")
#define CPA_WAIT1()  asm volatile("cp.async.wait_group 1;" ::: "memory")
#define CPA_WAIT0()  asm volatile("cp.async.wait_group 0;" ::: "memory")

__device__ __forceinline__ void ldsm4(uint32_t* r, uint32_t addr) {
    asm volatile("ldmatrix.sync.aligned.m8n8.x4.shared.b16 {%0,%1,%2,%3}, [%4];"
                 : "=r"(r[0]), "=r"(r[1]), "=r"(r[2]), "=r"(r[3]) : "r"(addr));
}

__device__ __forceinline__ void mma_bf16(float* c, const uint32_t* a, const uint32_t* b) {
    asm volatile(
        "mma.sync.aligned.m16n8k16.row.col.f32.bf16.bf16.f32 "
        "{%0,%1,%2,%3}, {%4,%5,%6,%7}, {%8,%9}, {%0,%1,%2,%3};"
        : "+f"(c[0]), "+f"(c[1]), "+f"(c[2]), "+f"(c[3])
        : "r"(a[0]), "r"(a[1]), "r"(a[2]), "r"(a[3]), "r"(b[0]), "r"(b[1]));
}

// ---------------------------------------------------------------------------
// fp32 -> bf16 hi/lo split
// ---------------------------------------------------------------------------
__global__ __launch_bounds__(256) void split_bf16(const float* __restrict__ src,
                                                  __nv_bfloat16* __restrict__ hi,
                                                  __nv_bfloat16* __restrict__ lo,
                                                  int n) {
    int i = (blockIdx.x * blockDim.x + threadIdx.x) * 4;
    if (i >= n) return;
    float4 v = *(const float4*)(src + i);
    float f[4] = {v.x, v.y, v.z, v.w};
    __nv_bfloat16 h[4], l[4];
    #pragma unroll
    for (int j = 0; j < 4; j++) {
        h[j] = __float2bfloat16(f[j]);
        l[j] = __float2bfloat16(f[j] - __bfloat162float(h[j]));
    }
    *(__nv_bfloat162*)(hi + i)     = __nv_bfloat162(h[0], h[1]);
    *(__nv_bfloat162*)(hi + i + 2) = __nv_bfloat162(h[2], h[3]);
    *(__nv_bfloat162*)(lo + i)     = __nv_bfloat162(l[0], l[1]);
    *(__nv_bfloat162*)(lo + i + 2) = __nv_bfloat162(l[2], l[3]);
}

// ---------------------------------------------------------------------------
// bf16x3 HMMA GEMM (NT): C[M,N] = (Ahi+Alo)[M,K] * (Bhi+Blo)[N,K]^T
// 128x128 CTA tile, Kc=32, 8 warps each 64x32 (4x4 m16n8k16 frags),
// cp.async double buffer, padded smem rows (40 bf16 = 80B, ldmatrix
// conflict-free), 3 MMA passes (hi*hi, hi*lo, lo*hi), fp32 accum.
// ---------------------------------------------------------------------------
#define KC 32
#define ROW_B 80                  // bytes per smem row (40 bf16)
#define TILE_B (128 * ROW_B)      // 10240
#define STAGE_B (4 * TILE_B)      // 40960 (Ah, Al, Bh, Bl)

__global__ __launch_bounds__(256) void gemm_hmma(
    const __nv_bfloat16* __restrict__ Ahi, const __nv_bfloat16* __restrict__ Alo,
    const __nv_bfloat16* __restrict__ Bhi, const __nv_bfloat16* __restrict__ Blo,
    float* __restrict__ C, int M, int N, int K) {
    extern __shared__ char sm[];
    const uint32_t sbase = smem_u32_of(sm);

    const int tid  = threadIdx.x;
    const int wid  = tid >> 5;
    const int lane = tid & 31;
    const int m0 = blockIdx.y * 128;
    const int n0 = blockIdx.x * 128;
    const int wm = wid >> 2;      // 0..1
    const int wn = wid & 3;       // 0..3

    // Loader: thread -> (row, 32B half of the 64B k-row)
    const int lrow  = tid >> 1;
    const int lhalf = tid & 1;
    const __nv_bfloat16* gAh = Ahi + (size_t)(m0 + lrow) * K + lhalf * 16;
    const __nv_bfloat16* gAl = Alo + (size_t)(m0 + lrow) * K + lhalf * 16;
    const __nv_bfloat16* gBh = Bhi + (size_t)(n0 + lrow) * K + lhalf * 16;
    const __nv_bfloat16* gBl = Blo + (size_t)(n0 + lrow) * K + lhalf * 16;
    const uint32_t so = (uint32_t)lrow * ROW_B + (uint32_t)lhalf * 32u;

    float acc[4][4][4] = {};
    const int NCH = K / KC;

    // issue loads for chunk c into stage s
    auto load_stage = [&](int c, int s) {
        const uint32_t st = sbase + (uint32_t)s * STAGE_B + so;
        const size_t go = (size_t)c * KC;
        CPA16(st,                        gAh + go);
        CPA16(st + 16,                   gAh + go + 8);
        CPA16(st + TILE_B,               gAl + go);
        CPA16(st + TILE_B + 16,          gAl + go + 8);
        CPA16(st + 2 * TILE_B,           gBh + go);
        CPA16(st + 2 * TILE_B + 16,      gBh + go + 8);
        CPA16(st + 3 * TILE_B,           gBl + go);
        CPA16(st + 3 * TILE_B + 16,      gBl + go + 8);
    };

    load_stage(0, 0);
    CPA_COMMIT();

    // fragment addresses (element coords precomputed)
    const int ar = wm * 64 + (lane & 15);            // A row within tile
    const int ac8 = (lane >> 4) * 8;                 // A col sub-offset
    const int br = wn * 32 + (lane & 7) + ((lane >> 4) << 3);  // B row (n)
    const int bc8 = ((lane >> 3) & 1) * 8;           // B col sub-offset

    for (int c = 0; c < NCH; c++) {
        const int s = c & 1;
        if (c + 1 < NCH) {
            load_stage(c + 1, s ^ 1);
            CPA_COMMIT();
            CPA_WAIT1();
        } else {
            CPA_WAIT0();
        }
        __syncthreads();

        const uint32_t Ah_b = sbase + (uint32_t)s * STAGE_B;
        const uint32_t Al_b = Ah_b + TILE_B;
        const uint32_t Bh_b = Ah_b + 2 * TILE_B;
        const uint32_t Bl_b = Ah_b + 3 * TILE_B;

        #pragma unroll
        for (int ks = 0; ks < 2; ks++) {
            const int ac = ks * 16 + ac8;
            const int bc = ks * 16 + bc8;
            uint32_t ah[4][4], al[4][4];
            #pragma unroll
            for (int mi = 0; mi < 4; mi++) {
                const uint32_t aoff = (uint32_t)(ar + mi * 16) * ROW_B + (uint32_t)ac * 2;
                ldsm4(ah[mi], Ah_b + aoff);
                ldsm4(al[mi], Al_b + aoff);
            }
            #pragma unroll
            for (int nj2 = 0; nj2 < 2; nj2++) {
                uint32_t bh[4], bl[4];
                const uint32_t boff = (uint32_t)(br + nj2 * 16) * ROW_B + (uint32_t)bc * 2;
                ldsm4(bh, Bh_b + boff);
                ldsm4(bl, Bl_b + boff);
                #pragma unroll
                for (int mi = 0; mi < 4; mi++) {
                    #pragma unroll
                    for (int j = 0; j < 2; j++) {
                        float* a4 = acc[mi][nj2 * 2 + j];
                        mma_bf16(a4, ah[mi], &bh[2 * j]);
                        mma_bf16(a4, ah[mi], &bl[2 * j]);
                        mma_bf16(a4, al[mi], &bh[2 * j]);
                    }
                }
            }
        }
        __syncthreads();
    }

    // Epilogue
    const int gr = lane >> 2;
    const int gc = (lane & 3) * 2;
    #pragma unroll
    for (int mi = 0; mi < 4; mi++) {
        #pragma unroll
        for (int nj = 0; nj < 4; nj++) {
            const int row = m0 + wm * 64 + mi * 16 + gr;
            const int col = n0 + wn * 32 + nj * 8 + gc;
            *(float2*)&C[(size_t)row * N + col] =
                make_float2(acc[mi][nj][0], acc[mi][nj][1]);
            *(float2*)&C[(size_t)(row + 8) * N + col] =
                make_float2(acc[mi][nj][2], acc[mi][nj][3]);
        }
    }
}

// ---------------------------------------------------------------------------
// Causal flash attention (fp32 FFMA). One block = (batch, head, 64-row q-tile).
// Emits bf16 hi/lo for the HMMA GEMM2.
// ---------------------------------------------------------------------------
__global__ __launch_bounds__(256) void flash_attn(const float* __restrict__ qkv,
                                                  __nv_bfloat16* __restrict__ out_hi,
                                                  __nv_bfloat16* __restrict__ out_lo) {
    const int qt = blockIdx.x;
    const int h  = blockIdx.y;
    const int b  = blockIdx.z;
    const int tid = threadIdx.x;
    const int tx = tid & 15;
    const int ty = tid >> 4;

    __shared__ float Qt[64][68];
    __shared__ float Kt[64][36];
    __shared__ float Vs[32][68];
    __shared__ float Ssm[64][36];
    __shared__ float rm[64], rl[64], rcorr[64];

    const int q0 = qt * 64;
    const size_t rstride = QKV_COLS;
    const float* qbase = qkv + ((size_t)b * TT + q0) * rstride + h * HD;

    #pragma unroll
    for (int i = 0; i < 4; i++) {
        int fl = tid + i * 256;
        int r  = fl >> 4;
        int c4 = (fl & 15) * 4;
        float4 v = *(const float4*)(qbase + (size_t)r * rstride + c4);
        Qt[c4 + 0][r] = v.x; Qt[c4 + 1][r] = v.y;
        Qt[c4 + 2][r] = v.z; Qt[c4 + 3][r] = v.w;
    }
    if (tid < 64) { rm[tid] = -1e30f; rl[tid] = 0.0f; }

    float o[4][4] = {};
    const int nkt = 2 * qt + 2;

    for (int kt = 0; kt < nkt; kt++) {
        __syncthreads();

        const float* kbase = qkv + ((size_t)b * TT + kt * 32) * rstride + HH + h * HD;
        const float* vbase = qkv + ((size_t)b * TT + kt * 32) * rstride + 2 * HH + h * HD;
        #pragma unroll
        for (int i = 0; i < 2; i++) {
            int fl = tid + i * 256;
            int r  = fl >> 4;
            int c4 = (fl & 15) * 4;
            float4 kv = *(const float4*)(kbase + (size_t)r * rstride + c4);
            Kt[c4 + 0][r] = kv.x; Kt[c4 + 1][r] = kv.y;
            Kt[c4 + 2][r] = kv.z; Kt[c4 + 3][r] = kv.w;
            float4 vv = *(const float4*)(vbase + (size_t)r * rstride + c4);
            *(float4*)&Vs[r][c4] = vv;
        }
        __syncthreads();

        {
            float acc[4][2] = {};
            #pragma unroll 16
            for (int d = 0; d < 64; d++) {
                float4 qf = *(const float4*)&Qt[d][ty * 4];
                float2 kf = *(const float2*)&Kt[d][tx * 2];
                acc[0][0] += qf.x * kf.x; acc[0][1] += qf.x * kf.y;
                acc[1][0] += qf.y * kf.x; acc[1][1] += qf.y * kf.y;
                acc[2][0] += qf.z * kf.x; acc[2][1] += qf.z * kf.y;
                acc[3][0] += qf.w * kf.x; acc[3][1] += qf.w * kf.y;
            }
            #pragma unroll
            for (int i = 0; i < 4; i++) {
                int qg = q0 + ty * 4 + i;
                #pragma unroll
                for (int j = 0; j < 2; j++) {
                    int kg = kt * 32 + tx * 2 + j;
                    float s = acc[i][j] * 0.125f;
                    if (kg > qg) s = -1e9f;
                    Ssm[ty * 4 + i][tx * 2 + j] = s;
                }
            }
        }
        __syncthreads();

        {
            int r = tid >> 2, sub = tid & 3;
            float* srow = &Ssm[r][sub * 8];
            float v[8];
            *(float4*)&v[0] = *(const float4*)&srow[0];
            *(float4*)&v[4] = *(const float4*)&srow[4];
            float vmax = v[0];
            #pragma unroll
            for (int j = 1; j < 8; j++) vmax = fmaxf(vmax, v[j]);
            vmax = fmaxf(vmax, __shfl_xor_sync(0xffffffffu, vmax, 1));
            vmax = fmaxf(vmax, __shfl_xor_sync(0xffffffffu, vmax, 2));
            float mold = rm[r];
            float mnew = fmaxf(mold, vmax);
            float sum = 0.0f;
            #pragma unroll
            for (int j = 0; j < 8; j++) {
                float p = __expf(v[j] - mnew);
                v[j] = p;
                sum += p;
            }
            *(float4*)&srow[0] = *(const float4*)&v[0];
            *(float4*)&srow[4] = *(const float4*)&v[4];
            sum += __shfl_xor_sync(0xffffffffu, sum, 1);
            sum += __shfl_xor_sync(0xffffffffu, sum, 2);
            float corr = __expf(mold - mnew);
            if (sub == 0) {
                rcorr[r] = corr;
                rl[r] = rl[r] * corr + sum;
                rm[r] = mnew;
            }
        }
        __syncthreads();

        {
            #pragma unroll
            for (int i = 0; i < 4; i++) {
                float cf = rcorr[ty * 4 + i];
                o[i][0] *= cf; o[i][1] *= cf; o[i][2] *= cf; o[i][3] *= cf;
            }
            #pragma unroll 8
            for (int kk = 0; kk < 32; kk++) {
                float4 vf = *(const float4*)&Vs[kk][tx * 4];
                #pragma unroll
                for (int i = 0; i < 4; i++) {
                    float p = Ssm[ty * 4 + i][kk];
                    o[i][0] += p * vf.x;
                    o[i][1] += p * vf.y;
                    o[i][2] += p * vf.z;
                    o[i][3] += p * vf.w;
                }
            }
        }
    }

    __nv_bfloat16* hbase = out_hi + ((size_t)b * TT + q0) * HH + h * HD;
    __nv_bfloat16* lbase = out_lo + ((size_t)b * TT + q0) * HH + h * HD;
    #pragma unroll
    for (int i = 0; i < 4; i++) {
        float inv = 1.0f / rl[ty * 4 + i];
        float v0 = o[i][0] * inv, v1 = o[i][1] * inv, v2 = o[i][2] * inv, v3 = o[i][3] * inv;
        __nv_bfloat16 h0 = __float2bfloat16(v0), h1 = __float2bfloat16(v1);
        __nv_bfloat16 h2 = __float2bfloat16(v2), h3 = __float2bfloat16(v3);
        __nv_bfloat16 l0 = __float2bfloat16(v0 - __bfloat162float(h0));
        __nv_bfloat16 l1 = __float2bfloat16(v1 - __bfloat162float(h1));
        __nv_bfloat16 l2 = __float2bfloat16(v2 - __bfloat162float(h2));
        __nv_bfloat16 l3 = __float2bfloat16(v3 - __bfloat162float(h3));
        size_t off = (size_t)(ty * 4 + i) * HH + tx * 4;
        *(__nv_bfloat162*)(hbase + off)     = __nv_bfloat162(h0, h1);
        *(__nv_bfloat162*)(hbase + off + 2) = __nv_bfloat162(h2, h3);
        *(__nv_bfloat162*)(lbase + off)     = __nv_bfloat162(l0, l1);
        *(__nv_bfloat162*)(lbase + off + 2) = __nv_bfloat162(l2, l3);
    }
}

// ---------------------------------------------------------------------------
extern "C" void kernel_launch(void* const* d_in, const int* in_sizes, int n_in,
                              void* d_out, int out_size) {
    const float* x    = (const float*)d_in[0];   // [4,2048,1024]
    const float* Wqkv = (const float*)d_in[1];   // [3072,1024]
    const float* Wout = (const float*)d_in[2];   // [1024,1024]
    float* out = (float*)d_out;                  // [4,2048,1024]

    float* qkv = nullptr;
    __nv_bfloat16 *xhi, *xlo, *wqh, *wql, *woh, *wol, *ahi, *alo;
    cudaGetSymbolAddress((void**)&qkv, g_qkv);
    cudaGetSymbolAddress((void**)&xhi, g_x_hi);
    cudaGetSymbolAddress((void**)&xlo, g_x_lo);
    cudaGetSymbolAddress((void**)&wqh, g_wqkv_hi);
    cudaGetSymbolAddress((void**)&wql, g_wqkv_lo);
    cudaGetSymbolAddress((void**)&woh, g_wout_hi);
    cudaGetSymbolAddress((void**)&wol, g_wout_lo);
    cudaGetSymbolAddress((void**)&ahi, g_attn_hi);
    cudaGetSymbolAddress((void**)&alo, g_attn_lo);

    cudaFuncSetAttribute(gemm_hmma, cudaFuncAttributeMaxDynamicSharedMemorySize,
                         2 * STAGE_B);

    // Split inputs into bf16 hi/lo
    {
        int n1 = ROWS * HH;
        split_bf16<<<(n1 / 4 + 255) / 256, 256>>>(x, xhi, xlo, n1);
        int n2 = QKV_COLS * HH;
        split_bf16<<<(n2 / 4 + 255) / 256, 256>>>(Wqkv, wqh, wql, n2);
        int n3 = HH * HH;
        split_bf16<<<(n3 / 4 + 255) / 256, 256>>>(Wout, woh, wol, n3);
    }

    // 1) qkv = x @ W_qkv^T
    gemm_hmma<<<dim3(QKV_COLS / 128, ROWS / 128), 256, 2 * STAGE_B>>>(
        xhi, xlo, wqh, wql, qkv, ROWS, QKV_COLS, HH);

    // 2) causal flash attention -> bf16 hi/lo
    flash_attn<<<dim3(TT / 64, NH, BB), 256>>>(qkv, ahi, alo);

    // 3) out = attn @ W_out^T
    gemm_hmma<<<dim3(HH / 128, ROWS / 128), 256, 2 * STAGE_B>>>(
        ahi, alo, woh, wol, out, ROWS, HH, HH);
}

// round 4
// speedup vs baseline: 2.4590x; 1.6488x over previous
#include <cuda_runtime.h>
#include <cuda_bf16.h>
#include <cstdint>

// Problem constants
#define BB 4
#define TT 2048
#define HH 1024
#define NH 16
#define HD 64
#define ROWS (BB*TT)          // 8192
#define QKV_COLS (3*HH)       // 3072

// Scratch (device globals; no runtime allocation allowed)
__device__ __nv_bfloat16 g_qkv_hi[(size_t)ROWS * QKV_COLS];
__device__ __nv_bfloat16 g_qkv_lo[(size_t)ROWS * QKV_COLS];
__device__ __nv_bfloat16 g_x_hi[(size_t)ROWS * HH];
__device__ __nv_bfloat16 g_x_lo[(size_t)ROWS * HH];
__device__ __nv_bfloat16 g_wqkv_hi[(size_t)QKV_COLS * HH];
__device__ __nv_bfloat16 g_wqkv_lo[(size_t)QKV_COLS * HH];
__device__ __nv_bfloat16 g_wout_hi[(size_t)HH * HH];
__device__ __nv_bfloat16 g_wout_lo[(size_t)HH * HH];
__device__ __nv_bfloat16 g_attn_hi[(size_t)ROWS * HH];
__device__ __nv_bfloat16 g_attn_lo[(size_t)ROWS * HH];

// ---------------------------------------------------------------------------
// Helpers
// ---------------------------------------------------------------------------
__device__ __forceinline__ uint32_t smem_u32_of(const void* p) {
    uint32_t a;
    asm("{ .reg .u64 t; cvta.to.shared.u64 t, %1; cvt.u32.u64 %0, t; }"
        : "=r"(a) : "l"(p));
    return a;
}

#define CPA16(dst, src) \
    asm volatile("cp.async.cg.shared.global [%0], [%1], 16;" :: "r"(dst), "l"(src))
#define CPA_COMMIT() asm volatile("cp.async.commit_group;" ::: "memory")
#define CPA_WAIT1()  asm volatile("cp.async.wait_group 1;" ::: "memory")
#define CPA_WAIT0()  asm volatile("cp.async.wait_group 0;" ::: "memory")

__device__ __forceinline__ void ldsm4(uint32_t* r, uint32_t addr) {
    asm volatile("ldmatrix.sync.aligned.m8n8.x4.shared.b16 {%0,%1,%2,%3}, [%4];"
                 : "=r"(r[0]), "=r"(r[1]), "=r"(r[2]), "=r"(r[3]) : "r"(addr));
}
__device__ __forceinline__ void ldsm4t(uint32_t* r, uint32_t addr) {
    asm volatile("ldmatrix.sync.aligned.m8n8.x4.trans.shared.b16 {%0,%1,%2,%3}, [%4];"
                 : "=r"(r[0]), "=r"(r[1]), "=r"(r[2]), "=r"(r[3]) : "r"(addr));
}

__device__ __forceinline__ void mma_bf16(float* c, const uint32_t* a, const uint32_t* b) {
    asm volatile(
        "mma.sync.aligned.m16n8k16.row.col.f32.bf16.bf16.f32 "
        "{%0,%1,%2,%3}, {%4,%5,%6,%7}, {%8,%9}, {%0,%1,%2,%3};"
        : "+f"(c[0]), "+f"(c[1]), "+f"(c[2]), "+f"(c[3])
        : "r"(a[0]), "r"(a[1]), "r"(a[2]), "r"(a[3]), "r"(b[0]), "r"(b[1]));
}

__device__ __forceinline__ float ex2f(float x) {
    float y;
    asm("ex2.approx.ftz.f32 %0, %1;" : "=f"(y) : "f"(x));
    return y;
}

__device__ __forceinline__ uint32_t pack_hi(float a, float b) {
    __nv_bfloat162 v(__float2bfloat16(a), __float2bfloat16(b));
    return *(uint32_t*)&v;
}
__device__ __forceinline__ uint32_t pack_lo(float a, float b) {
    __nv_bfloat16 ha = __float2bfloat16(a), hb = __float2bfloat16(b);
    __nv_bfloat162 v(__float2bfloat16(a - __bfloat162float(ha)),
                     __float2bfloat16(b - __bfloat162float(hb)));
    return *(uint32_t*)&v;
}

// ---------------------------------------------------------------------------
// fp32 -> bf16 hi/lo split
// ---------------------------------------------------------------------------
__global__ __launch_bounds__(256) void split_bf16(const float* __restrict__ src,
                                                  __nv_bfloat16* __restrict__ hi,
                                                  __nv_bfloat16* __restrict__ lo,
                                                  int n) {
    int i = (blockIdx.x * blockDim.x + threadIdx.x) * 4;
    if (i >= n) return;
    float4 v = *(const float4*)(src + i);
    float f[4] = {v.x, v.y, v.z, v.w};
    __nv_bfloat16 h[4], l[4];
    #pragma unroll
    for (int j = 0; j < 4; j++) {
        h[j] = __float2bfloat16(f[j]);
        l[j] = __float2bfloat16(f[j] - __bfloat162float(h[j]));
    }
    *(__nv_bfloat162*)(hi + i)     = __nv_bfloat162(h[0], h[1]);
    *(__nv_bfloat162*)(hi + i + 2) = __nv_bfloat162(h[2], h[3]);
    *(__nv_bfloat162*)(lo + i)     = __nv_bfloat162(l[0], l[1]);
    *(__nv_bfloat162*)(lo + i + 2) = __nv_bfloat162(l[2], l[3]);
}

// ---------------------------------------------------------------------------
// bf16x3 HMMA GEMM (NT): C = (Ahi+Alo) * (Bhi+Blo)^T, fp32 accum.
// SPLIT=false: write C fp32. SPLIT=true: write hi/lo bf16 pair arrays.
// ---------------------------------------------------------------------------
#define KC 32
#define ROW_B 80
#define TILE_B (128 * ROW_B)
#define STAGE_B (4 * TILE_B)

template <bool SPLIT>
__global__ __launch_bounds__(256) void gemm_hmma(
    const __nv_bfloat16* __restrict__ Ahi, const __nv_bfloat16* __restrict__ Alo,
    const __nv_bfloat16* __restrict__ Bhi, const __nv_bfloat16* __restrict__ Blo,
    float* __restrict__ C, __nv_bfloat16* __restrict__ Chi,
    __nv_bfloat16* __restrict__ Clo, int M, int N, int K) {
    extern __shared__ char sm[];
    const uint32_t sbase = smem_u32_of(sm);

    const int tid  = threadIdx.x;
    const int wid  = tid >> 5;
    const int lane = tid & 31;
    const int m0 = blockIdx.y * 128;
    const int n0 = blockIdx.x * 128;
    const int wm = wid >> 2;
    const int wn = wid & 3;

    const int lrow  = tid >> 1;
    const int lhalf = tid & 1;
    const __nv_bfloat16* gAh = Ahi + (size_t)(m0 + lrow) * K + lhalf * 16;
    const __nv_bfloat16* gAl = Alo + (size_t)(m0 + lrow) * K + lhalf * 16;
    const __nv_bfloat16* gBh = Bhi + (size_t)(n0 + lrow) * K + lhalf * 16;
    const __nv_bfloat16* gBl = Blo + (size_t)(n0 + lrow) * K + lhalf * 16;
    const uint32_t so = (uint32_t)lrow * ROW_B + (uint32_t)lhalf * 32u;

    float acc[4][4][4] = {};
    const int NCH = K / KC;

    auto load_stage = [&](int c, int s) {
        const uint32_t st = sbase + (uint32_t)s * STAGE_B + so;
        const size_t go = (size_t)c * KC;
        CPA16(st,                   gAh + go);
        CPA16(st + 16,              gAh + go + 8);
        CPA16(st + TILE_B,          gAl + go);
        CPA16(st + TILE_B + 16,     gAl + go + 8);
        CPA16(st + 2 * TILE_B,      gBh + go);
        CPA16(st + 2 * TILE_B + 16, gBh + go + 8);
        CPA16(st + 3 * TILE_B,      gBl + go);
        CPA16(st + 3 * TILE_B + 16, gBl + go + 8);
    };

    load_stage(0, 0);
    CPA_COMMIT();

    const int ar = wm * 64 + (lane & 15);
    const int ac8 = (lane >> 4) * 8;
    const int br = wn * 32 + (lane & 7) + ((lane >> 4) << 3);
    const int bc8 = ((lane >> 3) & 1) * 8;

    for (int c = 0; c < NCH; c++) {
        const int s = c & 1;
        if (c + 1 < NCH) {
            load_stage(c + 1, s ^ 1);
            CPA_COMMIT();
            CPA_WAIT1();
        } else {
            CPA_WAIT0();
        }
        __syncthreads();

        const uint32_t Ah_b = sbase + (uint32_t)s * STAGE_B;
        const uint32_t Al_b = Ah_b + TILE_B;
        const uint32_t Bh_b = Ah_b + 2 * TILE_B;
        const uint32_t Bl_b = Ah_b + 3 * TILE_B;

        #pragma unroll
        for (int ks = 0; ks < 2; ks++) {
            const int ac = ks * 16 + ac8;
            const int bc = ks * 16 + bc8;
            uint32_t ah[4][4], al[4][4];
            #pragma unroll
            for (int mi = 0; mi < 4; mi++) {
                const uint32_t aoff = (uint32_t)(ar + mi * 16) * ROW_B + (uint32_t)ac * 2;
                ldsm4(ah[mi], Ah_b + aoff);
                ldsm4(al[mi], Al_b + aoff);
            }
            #pragma unroll
            for (int nj2 = 0; nj2 < 2; nj2++) {
                uint32_t bh[4], bl[4];
                const uint32_t boff = (uint32_t)(br + nj2 * 16) * ROW_B + (uint32_t)bc * 2;
                ldsm4(bh, Bh_b + boff);
                ldsm4(bl, Bl_b + boff);
                #pragma unroll
                for (int mi = 0; mi < 4; mi++) {
                    #pragma unroll
                    for (int j = 0; j < 2; j++) {
                        float* a4 = acc[mi][nj2 * 2 + j];
                        mma_bf16(a4, ah[mi], &bh[2 * j]);
                        mma_bf16(a4, ah[mi], &bl[2 * j]);
                        mma_bf16(a4, al[mi], &bh[2 * j]);
                    }
                }
            }
        }
        __syncthreads();
    }

    const int gr = lane >> 2;
    const int gc = (lane & 3) * 2;
    #pragma unroll
    for (int mi = 0; mi < 4; mi++) {
        #pragma unroll
        for (int nj = 0; nj < 4; nj++) {
            const int row = m0 + wm * 64 + mi * 16 + gr;
            const int col = n0 + wn * 32 + nj * 8 + gc;
            if (SPLIT) {
                *(uint32_t*)&Chi[(size_t)row * N + col] = pack_hi(acc[mi][nj][0], acc[mi][nj][1]);
                *(uint32_t*)&Clo[(size_t)row * N + col] = pack_lo(acc[mi][nj][0], acc[mi][nj][1]);
                *(uint32_t*)&Chi[(size_t)(row + 8) * N + col] = pack_hi(acc[mi][nj][2], acc[mi][nj][3]);
                *(uint32_t*)&Clo[(size_t)(row + 8) * N + col] = pack_lo(acc[mi][nj][2], acc[mi][nj][3]);
            } else {
                *(float2*)&C[(size_t)row * N + col] =
                    make_float2(acc[mi][nj][0], acc[mi][nj][1]);
                *(float2*)&C[(size_t)(row + 8) * N + col] =
                    make_float2(acc[mi][nj][2], acc[mi][nj][3]);
            }
        }
    }
}

// ---------------------------------------------------------------------------
// Tensor-core causal flash attention (bf16x3 on both MMAs).
// One CTA = (64-row q-tile, head, batch), 4 warps, k-tiles of 64.
// qkv hi/lo layout: [B*T, 3H]; q cols h*64, k at HH+h*64, v at 2*HH+h*64.
// ---------------------------------------------------------------------------
#define FA_STR 144                 // bytes per smem row (64 bf16 + 8 pad)
#define FA_T   (64 * FA_STR)       // 9216 bytes per tensor tile
#define FA_SMEM (10 * FA_T)        // Qhi,Qlo + 2 stages x (Khi,Klo,Vhi,Vlo)

__global__ __launch_bounds__(128) void flash_tc(
    const __nv_bfloat16* __restrict__ qkh, const __nv_bfloat16* __restrict__ qkl,
    __nv_bfloat16* __restrict__ oh, __nv_bfloat16* __restrict__ ol) {
    extern __shared__ char sm[];
    const uint32_t sb = smem_u32_of(sm);
    const int qt = (int)gridDim.x - 1 - (int)blockIdx.x;   // big tiles first
    const int h  = blockIdx.y;
    const int b  = blockIdx.z;
    const int tid = threadIdx.x;
    const int w = tid >> 5;
    const int l = tid & 31;

    const int r  = tid >> 1;
    const int hf = tid & 1;

    // Q load (hi/lo)
    {
        const size_t qoff = ((size_t)(b * TT + qt * 64 + r)) * QKV_COLS + h * HD + hf * 32;
        const uint32_t d0 = sb + (uint32_t)r * FA_STR + (uint32_t)hf * 64;
        #pragma unroll
        for (int i = 0; i < 4; i++) {
            CPA16(d0 + 16 * i,        qkh + qoff + 8 * i);
            CPA16(d0 + FA_T + 16 * i, qkl + qoff + 8 * i);
        }
    }

    auto load_kv = [&](int kt, int s) {
        const size_t koff = ((size_t)(b * TT + kt * 64 + r)) * QKV_COLS + HH + h * HD + hf * 32;
        const size_t voff = koff + HH;
        const uint32_t d = sb + 2 * FA_T + (uint32_t)s * 4 * FA_T
                         + (uint32_t)r * FA_STR + (uint32_t)hf * 64;
        #pragma unroll
        for (int i = 0; i < 4; i++) {
            CPA16(d + 16 * i,            qkh + koff + 8 * i);
            CPA16(d + FA_T + 16 * i,     qkl + koff + 8 * i);
            CPA16(d + 2 * FA_T + 16 * i, qkh + voff + 8 * i);
            CPA16(d + 3 * FA_T + 16 * i, qkl + voff + 8 * i);
        }
    };

    load_kv(0, 0);
    CPA_COMMIT();

    float o[8][4] = {};
    float m0 = -1e30f, m1 = -1e30f, l0 = 0.0f, l1 = 0.0f;
    uint32_t qfh[4][4], qfl[4][4];
    const int nkt = qt + 1;
    const float SCL = 0.18033688011112042f;    // (1/8) * log2(e)

    const uint32_t qa = sb + (uint32_t)(w * 16 + (l & 15)) * FA_STR + (uint32_t)((l >> 4) * 8) * 2;
    const uint32_t kb_row = (uint32_t)((l & 7) + ((l >> 4) << 3)) * FA_STR
                          + (uint32_t)(((l >> 3) & 1) * 8) * 2;
    const uint32_t vb_row = (uint32_t)((l & 7) + (((l >> 3) & 1) << 3)) * FA_STR
                          + (uint32_t)((l >> 4) * 8) * 2;

    const int lr0 = w * 16 + (l >> 2);
    const int cb  = (l & 3) * 2;

    for (int kt = 0; kt < nkt; kt++) {
        const int s = kt & 1;
        if (kt + 1 < nkt) {
            load_kv(kt + 1, s ^ 1);
            CPA_COMMIT();
            CPA_WAIT1();
        } else {
            CPA_WAIT0();
        }
        __syncthreads();

        if (kt == 0) {
            #pragma unroll
            for (int ks = 0; ks < 4; ks++) {
                ldsm4(qfh[ks], qa + ks * 32);
                ldsm4(qfl[ks], qa + FA_T + ks * 32);
            }
        }

        const uint32_t Kb = sb + 2 * FA_T + (uint32_t)s * 4 * FA_T;
        const uint32_t Vb = Kb + 2 * FA_T;

        // S = Q K^T (bf16x3)
        float sc[8][4] = {};
        #pragma unroll
        for (int g = 0; g < 4; g++) {
            #pragma unroll
            for (int ks = 0; ks < 4; ks++) {
                uint32_t bh[4], bl[4];
                const uint32_t ad = Kb + (uint32_t)(g * 16) * FA_STR + kb_row + ks * 32;
                ldsm4(bh, ad);
                ldsm4(bl, ad + FA_T);
                mma_bf16(sc[2 * g],     qfh[ks], &bh[0]);
                mma_bf16(sc[2 * g],     qfh[ks], &bl[0]);
                mma_bf16(sc[2 * g],     qfl[ks], &bh[0]);
                mma_bf16(sc[2 * g + 1], qfh[ks], &bh[2]);
                mma_bf16(sc[2 * g + 1], qfh[ks], &bl[2]);
                mma_bf16(sc[2 * g + 1], qfl[ks], &bh[2]);
            }
        }

        // scale + causal mask (diagonal tile only)
        const bool diag = (kt == qt);
        float mx0 = -1e30f, mx1 = -1e30f;
        #pragma unroll
        for (int j = 0; j < 8; j++) {
            float s0 = sc[j][0] * SCL, s1 = sc[j][1] * SCL;
            float s2 = sc[j][2] * SCL, s3 = sc[j][3] * SCL;
            if (diag) {
                const int c = j * 8 + cb;
                if (c     > lr0)     s0 = -1e30f;
                if (c + 1 > lr0)     s1 = -1e30f;
                if (c     > lr0 + 8) s2 = -1e30f;
                if (c + 1 > lr0 + 8) s3 = -1e30f;
            }
            sc[j][0] = s0; sc[j][1] = s1; sc[j][2] = s2; sc[j][3] = s3;
            mx0 = fmaxf(mx0, fmaxf(s0, s1));
            mx1 = fmaxf(mx1, fmaxf(s2, s3));
        }
        mx0 = fmaxf(mx0, __shfl_xor_sync(0xffffffffu, mx0, 1));
        mx0 = fmaxf(mx0, __shfl_xor_sync(0xffffffffu, mx0, 2));
        mx1 = fmaxf(mx1, __shfl_xor_sync(0xffffffffu, mx1, 1));
        mx1 = fmaxf(mx1, __shfl_xor_sync(0xffffffffu, mx1, 2));

        const float mn0 = fmaxf(m0, mx0);
        const float mn1 = fmaxf(m1, mx1);
        const float corr0 = ex2f(m0 - mn0);
        const float corr1 = ex2f(m1 - mn1);
        float sum0 = 0.0f, sum1 = 0.0f;
        #pragma unroll
        for (int j = 0; j < 8; j++) {
            sc[j][0] = ex2f(sc[j][0] - mn0); sum0 += sc[j][0];
            sc[j][1] = ex2f(sc[j][1] - mn0); sum0 += sc[j][1];
            sc[j][2] = ex2f(sc[j][2] - mn1); sum1 += sc[j][2];
            sc[j][3] = ex2f(sc[j][3] - mn1); sum1 += sc[j][3];
        }
        sum0 += __shfl_xor_sync(0xffffffffu, sum0, 1);
        sum0 += __shfl_xor_sync(0xffffffffu, sum0, 2);
        sum1 += __shfl_xor_sync(0xffffffffu, sum1, 1);
        sum1 += __shfl_xor_sync(0xffffffffu, sum1, 2);
        l0 = l0 * corr0 + sum0;
        l1 = l1 * corr1 + sum1;
        m0 = mn0; m1 = mn1;

        #pragma unroll
        for (int j = 0; j < 8; j++) {
            o[j][0] *= corr0; o[j][1] *= corr0;
            o[j][2] *= corr1; o[j][3] *= corr1;
        }

        // P fragments (hi/lo) from S accumulators
        uint32_t pah[4][4], pal[4][4];
        #pragma unroll
        for (int ks = 0; ks < 4; ks++) {
            pah[ks][0] = pack_hi(sc[2 * ks][0],     sc[2 * ks][1]);
            pal[ks][0] = pack_lo(sc[2 * ks][0],     sc[2 * ks][1]);
            pah[ks][1] = pack_hi(sc[2 * ks][2],     sc[2 * ks][3]);
            pal[ks][1] = pack_lo(sc[2 * ks][2],     sc[2 * ks][3]);
            pah[ks][2] = pack_hi(sc[2 * ks + 1][0], sc[2 * ks + 1][1]);
            pal[ks][2] = pack_lo(sc[2 * ks + 1][0], sc[2 * ks + 1][1]);
            pah[ks][3] = pack_hi(sc[2 * ks + 1][2], sc[2 * ks + 1][3]);
            pal[ks][3] = pack_lo(sc[2 * ks + 1][2], sc[2 * ks + 1][3]);
        }

        // O += P V (bf16x3), V via ldmatrix.trans
        #pragma unroll
        for (int g = 0; g < 4; g++) {
            #pragma unroll
            for (int ks = 0; ks < 4; ks++) {
                uint32_t vh[4], vl[4];
                const uint32_t ad = Vb + (uint32_t)(ks * 16) * FA_STR + vb_row + g * 32;
                ldsm4t(vh, ad);
                ldsm4t(vl, ad + FA_T);
                mma_bf16(o[2 * g],     pah[ks], &vh[0]);
                mma_bf16(o[2 * g],     pah[ks], &vl[0]);
                mma_bf16(o[2 * g],     pal[ks], &vh[0]);
                mma_bf16(o[2 * g + 1], pah[ks], &vh[2]);
                mma_bf16(o[2 * g + 1], pah[ks], &vl[2]);
                mma_bf16(o[2 * g + 1], pal[ks], &vh[2]);
            }
        }
        __syncthreads();
    }

    // Epilogue: normalize + write hi/lo bf16
    const float i0 = 1.0f / l0;
    const float i1 = 1.0f / l1;
    const size_t row0 = (size_t)(b * TT + qt * 64 + w * 16 + (l >> 2));
    const size_t row1 = row0 + 8;
    const int colb = h * HD + cb;
    #pragma unroll
    for (int j = 0; j < 8; j++) {
        const size_t c = colb + j * 8;
        const float v0 = o[j][0] * i0, v1 = o[j][1] * i0;
        const float v2 = o[j][2] * i1, v3 = o[j][3] * i1;
        *(uint32_t*)&oh[row0 * HH + c] = pack_hi(v0, v1);
        *(uint32_t*)&ol[row0 * HH + c] = pack_lo(v0, v1);
        *(uint32_t*)&oh[row1 * HH + c] = pack_hi(v2, v3);
        *(uint32_t*)&ol[row1 * HH + c] = pack_lo(v2, v3);
    }
}

// ---------------------------------------------------------------------------
extern "C" void kernel_launch(void* const* d_in, const int* in_sizes, int n_in,
                              void* d_out, int out_size) {
    const float* x    = (const float*)d_in[0];   // [4,2048,1024]
    const float* Wqkv = (const float*)d_in[1];   // [3072,1024]
    const float* Wout = (const float*)d_in[2];   // [1024,1024]
    float* out = (float*)d_out;                  // [4,2048,1024]

    __nv_bfloat16 *qh, *ql, *xhi, *xlo, *wqh, *wql, *woh, *wol, *ahi, *alo;
    cudaGetSymbolAddress((void**)&qh,  g_qkv_hi);
    cudaGetSymbolAddress((void**)&ql,  g_qkv_lo);
    cudaGetSymbolAddress((void**)&xhi, g_x_hi);
    cudaGetSymbolAddress((void**)&xlo, g_x_lo);
    cudaGetSymbolAddress((void**)&wqh, g_wqkv_hi);
    cudaGetSymbolAddress((void**)&wql, g_wqkv_lo);
    cudaGetSymbolAddress((void**)&woh, g_wout_hi);
    cudaGetSymbolAddress((void**)&wol, g_wout_lo);
    cudaGetSymbolAddress((void**)&ahi, g_attn_hi);
    cudaGetSymbolAddress((void**)&alo, g_attn_lo);

    cudaFuncSetAttribute(gemm_hmma<true>,  cudaFuncAttributeMaxDynamicSharedMemorySize, 2 * STAGE_B);
    cudaFuncSetAttribute(gemm_hmma<false>, cudaFuncAttributeMaxDynamicSharedMemorySize, 2 * STAGE_B);
    cudaFuncSetAttribute(flash_tc, cudaFuncAttributeMaxDynamicSharedMemorySize, FA_SMEM);

    // Split inputs into bf16 hi/lo
    {
        int n1 = ROWS * HH;
        split_bf16<<<(n1 / 4 + 255) / 256, 256>>>(x, xhi, xlo, n1);
        int n2 = QKV_COLS * HH;
        split_bf16<<<(n2 / 4 + 255) / 256, 256>>>(Wqkv, wqh, wql, n2);
        int n3 = HH * HH;
        split_bf16<<<(n3 / 4 + 255) / 256, 256>>>(Wout, woh, wol, n3);
    }

    // 1) qkv = x @ W_qkv^T -> bf16 hi/lo directly
    gemm_hmma<true><<<dim3(QKV_COLS / 128, ROWS / 128), 256, 2 * STAGE_B>>>(
        xhi, xlo, wqh, wql, nullptr, qh, ql, ROWS, QKV_COLS, HH);

    // 2) tensor-core causal flash attention -> bf16 hi/lo
    flash_tc<<<dim3(TT / 64, NH, BB), 128, FA_SMEM>>>(qh, ql, ahi, alo);

    // 3) out = attn @ W_out^T -> fp32
    gemm_hmma<false><<<dim3(HH / 128, ROWS / 128), 256, 2 * STAGE_B>>>(
        ahi, alo, woh, wol, out, nullptr, nullptr, ROWS, HH, HH);
}

// round 7
// speedup vs baseline: 2.6311x; 1.0700x over previous
#include <cuda_runtime.h>
#include <cuda_bf16.h>
#include <cstdint>

// Problem constants
#define BB 4
#define TT 2048
#define HH 1024
#define NH 16
#define HD 64
#define ROWS (BB*TT)          // 8192
#define QKV_COLS (3*HH)       // 3072

// Scratch (device globals; no runtime allocation allowed)
__device__ __nv_bfloat16 g_qkv_hi[(size_t)ROWS * QKV_COLS];
__device__ __nv_bfloat16 g_qkv_lo[(size_t)ROWS * QKV_COLS];
__device__ __nv_bfloat16 g_x_hi[(size_t)ROWS * HH];
__device__ __nv_bfloat16 g_x_lo[(size_t)ROWS * HH];
__device__ __nv_bfloat16 g_wqkv_hi[(size_t)QKV_COLS * HH];
__device__ __nv_bfloat16 g_wqkv_lo[(size_t)QKV_COLS * HH];
__device__ __nv_bfloat16 g_wout_hi[(size_t)HH * HH];
__device__ __nv_bfloat16 g_wout_lo[(size_t)HH * HH];
__device__ __nv_bfloat16 g_attn_hi[(size_t)ROWS * HH];
__device__ __nv_bfloat16 g_attn_lo[(size_t)ROWS * HH];

// ---------------------------------------------------------------------------
// Helpers
// ---------------------------------------------------------------------------
__device__ __forceinline__ uint32_t smem_u32_of(const void* p) {
    uint32_t a;
    asm("{ .reg .u64 t; cvta.to.shared.u64 t, %1; cvt.u32.u64 %0, t; }"
        : "=r"(a) : "l"(p));
    return a;
}

#define CPA16(dst, src) \
    asm volatile("cp.async.cg.shared.global [%0], [%1], 16;" :: "r"(dst), "l"(src))
#define CPA_COMMIT() asm volatile("cp.async.commit_group;" ::: "memory")
#define CPA_WAIT1()  asm volatile("cp.async.wait_group 1;" ::: "memory")
#define CPA_WAIT0()  asm volatile("cp.async.wait_group 0;" ::: "memory")

__device__ __forceinline__ void ldsm4(uint32_t* r, uint32_t addr) {
    asm volatile("ldmatrix.sync.aligned.m8n8.x4.shared.b16 {%0,%1,%2,%3}, [%4];"
                 : "=r"(r[0]), "=r"(r[1]), "=r"(r[2]), "=r"(r[3]) : "r"(addr));
}
__device__ __forceinline__ void ldsm4t(uint32_t* r, uint32_t addr) {
    asm volatile("ldmatrix.sync.aligned.m8n8.x4.trans.shared.b16 {%0,%1,%2,%3}, [%4];"
                 : "=r"(r[0]), "=r"(r[1]), "=r"(r[2]), "=r"(r[3]) : "r"(addr));
}

__device__ __forceinline__ void mma_bf16(float* c, const uint32_t* a, const uint32_t* b) {
    asm volatile(
        "mma.sync.aligned.m16n8k16.row.col.f32.bf16.bf16.f32 "
        "{%0,%1,%2,%3}, {%4,%5,%6,%7}, {%8,%9}, {%0,%1,%2,%3};"
        : "+f"(c[0]), "+f"(c[1]), "+f"(c[2]), "+f"(c[3])
        : "r"(a[0]), "r"(a[1]), "r"(a[2]), "r"(a[3]), "r"(b[0]), "r"(b[1]));
}

__device__ __forceinline__ float ex2f(float x) {
    float y;
    asm("ex2.approx.ftz.f32 %0, %1;" : "=f"(y) : "f"(x));
    return y;
}

__device__ __forceinline__ uint32_t pack_hi(float a, float b) {
    __nv_bfloat162 v(__float2bfloat16(a), __float2bfloat16(b));
    return *(uint32_t*)&v;
}
__device__ __forceinline__ uint32_t pack_lo(float a, float b) {
    __nv_bfloat16 ha = __float2bfloat16(a), hb = __float2bfloat16(b);
    __nv_bfloat162 v(__float2bfloat16(a - __bfloat162float(ha)),
                     __float2bfloat16(b - __bfloat162float(hb)));
    return *(uint32_t*)&v;
}

// ---------------------------------------------------------------------------
// fp32 -> bf16 hi/lo split
// ---------------------------------------------------------------------------
__global__ __launch_bounds__(256) void split_bf16(const float* __restrict__ src,
                                                  __nv_bfloat16* __restrict__ hi,
                                                  __nv_bfloat16* __restrict__ lo,
                                                  int n) {
    int i = (blockIdx.x * blockDim.x + threadIdx.x) * 4;
    if (i >= n) return;
    float4 v = *(const float4*)(src + i);
    float f[4] = {v.x, v.y, v.z, v.w};
    __nv_bfloat16 h[4], l[4];
    #pragma unroll
    for (int j = 0; j < 4; j++) {
        h[j] = __float2bfloat16(f[j]);
        l[j] = __float2bfloat16(f[j] - __bfloat162float(h[j]));
    }
    *(__nv_bfloat162*)(hi + i)     = __nv_bfloat162(h[0], h[1]);
    *(__nv_bfloat162*)(hi + i + 2) = __nv_bfloat162(h[2], h[3]);
    *(__nv_bfloat162*)(lo + i)     = __nv_bfloat162(l[0], l[1]);
    *(__nv_bfloat162*)(lo + i + 2) = __nv_bfloat162(l[2], l[3]);
}

// ---------------------------------------------------------------------------
// bf16x3 HMMA GEMM (NT): C = (Ahi+Alo) * (Bhi+Blo)^T, fp32 accum.
// SPLIT=false: write C fp32. SPLIT=true: write hi/lo bf16 pair arrays.
// B fragments hoisted per k-step so LDSM latency overlaps MMA issue.
// ---------------------------------------------------------------------------
#define KC 32
#define ROW_B 80
#define TILE_B (128 * ROW_B)
#define STAGE_B (4 * TILE_B)

template <bool SPLIT>
__global__ __launch_bounds__(256) void gemm_hmma(
    const __nv_bfloat16* __restrict__ Ahi, const __nv_bfloat16* __restrict__ Alo,
    const __nv_bfloat16* __restrict__ Bhi, const __nv_bfloat16* __restrict__ Blo,
    float* __restrict__ C, __nv_bfloat16* __restrict__ Chi,
    __nv_bfloat16* __restrict__ Clo, int M, int N, int K) {
    extern __shared__ char sm[];
    const uint32_t sbase = smem_u32_of(sm);

    const int tid  = threadIdx.x;
    const int wid  = tid >> 5;
    const int lane = tid & 31;
    const int m0 = blockIdx.y * 128;
    const int n0 = blockIdx.x * 128;
    const int wm = wid >> 2;
    const int wn = wid & 3;

    const int lrow  = tid >> 1;
    const int lhalf = tid & 1;
    const __nv_bfloat16* gAh = Ahi + (size_t)(m0 + lrow) * K + lhalf * 16;
    const __nv_bfloat16* gAl = Alo + (size_t)(m0 + lrow) * K + lhalf * 16;
    const __nv_bfloat16* gBh = Bhi + (size_t)(n0 + lrow) * K + lhalf * 16;
    const __nv_bfloat16* gBl = Blo + (size_t)(n0 + lrow) * K + lhalf * 16;
    const uint32_t so = (uint32_t)lrow * ROW_B + (uint32_t)lhalf * 32u;

    float acc[4][4][4] = {};
    const int NCH = K / KC;

    auto load_stage = [&](int c, int s) {
        const uint32_t st = sbase + (uint32_t)s * STAGE_B + so;
        const size_t go = (size_t)c * KC;
        CPA16(st,                   gAh + go);
        CPA16(st + 16,              gAh + go + 8);
        CPA16(st + TILE_B,          gAl + go);
        CPA16(st + TILE_B + 16,     gAl + go + 8);
        CPA16(st + 2 * TILE_B,      gBh + go);
        CPA16(st + 2 * TILE_B + 16, gBh + go + 8);
        CPA16(st + 3 * TILE_B,      gBl + go);
        CPA16(st + 3 * TILE_B + 16, gBl + go + 8);
    };

    load_stage(0, 0);
    CPA_COMMIT();

    const int ar = wm * 64 + (lane & 15);
    const int ac8 = (lane >> 4) * 8;
    const int br = wn * 32 + (lane & 7) + ((lane >> 4) << 3);
    const int bc8 = ((lane >> 3) & 1) * 8;

    for (int c = 0; c < NCH; c++) {
        const int s = c & 1;
        if (c + 1 < NCH) {
            load_stage(c + 1, s ^ 1);
            CPA_COMMIT();
            CPA_WAIT1();
        } else {
            CPA_WAIT0();
        }
        __syncthreads();

        const uint32_t Ah_b = sbase + (uint32_t)s * STAGE_B;
        const uint32_t Al_b = Ah_b + TILE_B;
        const uint32_t Bh_b = Ah_b + 2 * TILE_B;
        const uint32_t Bl_b = Ah_b + 3 * TILE_B;

        #pragma unroll
        for (int ks = 0; ks < 2; ks++) {
            const int ac = ks * 16 + ac8;
            const int bc = ks * 16 + bc8;
            // hoist ALL fragments for this k-step before any MMA
            uint32_t bh[2][4], bl[2][4];
            #pragma unroll
            for (int nj2 = 0; nj2 < 2; nj2++) {
                const uint32_t boff = (uint32_t)(br + nj2 * 16) * ROW_B + (uint32_t)bc * 2;
                ldsm4(bh[nj2], Bh_b + boff);
                ldsm4(bl[nj2], Bl_b + boff);
            }
            uint32_t ah[4][4], al[4][4];
            #pragma unroll
            for (int mi = 0; mi < 4; mi++) {
                const uint32_t aoff = (uint32_t)(ar + mi * 16) * ROW_B + (uint32_t)ac * 2;
                ldsm4(ah[mi], Ah_b + aoff);
                ldsm4(al[mi], Al_b + aoff);
            }
            #pragma unroll
            for (int nj2 = 0; nj2 < 2; nj2++) {
                #pragma unroll
                for (int mi = 0; mi < 4; mi++) {
                    #pragma unroll
                    for (int j = 0; j < 2; j++) {
                        float* a4 = acc[mi][nj2 * 2 + j];
                        mma_bf16(a4, ah[mi], &bh[nj2][2 * j]);
                        mma_bf16(a4, ah[mi], &bl[nj2][2 * j]);
                        mma_bf16(a4, al[mi], &bh[nj2][2 * j]);
                    }
                }
            }
        }
        __syncthreads();
    }

    const int gr = lane >> 2;
    const int gc = (lane & 3) * 2;
    #pragma unroll
    for (int mi = 0; mi < 4; mi++) {
        #pragma unroll
        for (int nj = 0; nj < 4; nj++) {
            const int row = m0 + wm * 64 + mi * 16 + gr;
            const int col = n0 + wn * 32 + nj * 8 + gc;
            if (SPLIT) {
                *(uint32_t*)&Chi[(size_t)row * N + col] = pack_hi(acc[mi][nj][0], acc[mi][nj][1]);
                *(uint32_t*)&Clo[(size_t)row * N + col] = pack_lo(acc[mi][nj][0], acc[mi][nj][1]);
                *(uint32_t*)&Chi[(size_t)(row + 8) * N + col] = pack_hi(acc[mi][nj][2], acc[mi][nj][3]);
                *(uint32_t*)&Clo[(size_t)(row + 8) * N + col] = pack_lo(acc[mi][nj][2], acc[mi][nj][3]);
            } else {
                *(float2*)&C[(size_t)row * N + col] =
                    make_float2(acc[mi][nj][0], acc[mi][nj][1]);
                *(float2*)&C[(size_t)(row + 8) * N + col] =
                    make_float2(acc[mi][nj][2], acc[mi][nj][3]);
            }
        }
    }
}

// ---------------------------------------------------------------------------
// Tensor-core causal flash attention (bf16x3 both MMAs).
// One CTA = (128-row q-tile, head, batch), 8 warps (16 q-rows each),
// k-tiles of 64, double-buffered K/V via cp.async.
// ---------------------------------------------------------------------------
#define FA_STR 144                  // bytes per smem row (64 bf16 + 8 pad)
#define FA_QT  (128 * FA_STR)       // 18432  (Q tile: 128 rows)
#define FA_KT  (64 * FA_STR)        // 9216   (K/V tile: 64 rows)
#define FA_SMEM (2 * FA_QT + 2 * 4 * FA_KT)   // 110592

__global__ __launch_bounds__(256) void flash_tc(
    const __nv_bfloat16* __restrict__ qkh, const __nv_bfloat16* __restrict__ qkl,
    __nv_bfloat16* __restrict__ oh, __nv_bfloat16* __restrict__ ol) {
    extern __shared__ char sm[];
    const uint32_t sb = smem_u32_of(sm);
    const int qt = (int)gridDim.x - 1 - (int)blockIdx.x;   // long tiles first
    const int h  = blockIdx.y;
    const int b  = blockIdx.z;
    const int tid = threadIdx.x;
    const int w = tid >> 5;
    const int l = tid & 31;

    // Q load: 128 rows, thread -> (row = tid>>1, 64B half)
    {
        const int r  = tid >> 1;
        const int hf = tid & 1;
        const size_t qoff = ((size_t)(b * TT + qt * 128 + r)) * QKV_COLS + h * HD + hf * 32;
        const uint32_t d0 = sb + (uint32_t)r * FA_STR + (uint32_t)hf * 64;
        #pragma unroll
        for (int i = 0; i < 4; i++) {
            CPA16(d0 + 16 * i,         qkh + qoff + 8 * i);
            CPA16(d0 + FA_QT + 16 * i, qkl + qoff + 8 * i);
        }
    }

    // K/V load: 64 rows, thread -> (row = tid>>2, 32B quarter)
    const int kr = tid >> 2;
    const int kq = tid & 3;
    auto load_kv = [&](int kt, int s) {
        const size_t koff = ((size_t)(b * TT + kt * 64 + kr)) * QKV_COLS + HH + h * HD + kq * 16;
        const size_t voff = koff + HH;
        const uint32_t d = sb + 2 * FA_QT + (uint32_t)s * 4 * FA_KT
                         + (uint32_t)kr * FA_STR + (uint32_t)kq * 32;
        CPA16(d,                 qkh + koff);
        CPA16(d + 16,            qkh + koff + 8);
        CPA16(d + FA_KT,         qkl + koff);
        CPA16(d + FA_KT + 16,    qkl + koff + 8);
        CPA16(d + 2 * FA_KT,      qkh + voff);
        CPA16(d + 2 * FA_KT + 16, qkh + voff + 8);
        CPA16(d + 3 * FA_KT,      qkl + voff);
        CPA16(d + 3 * FA_KT + 16, qkl + voff + 8);
    };

    load_kv(0, 0);
    CPA_COMMIT();

    float o[8][4] = {};
    float m0 = -1e30f, m1 = -1e30f, l0 = 0.0f, l1 = 0.0f;
    uint32_t qfh[4][4], qfl[4][4];
    const int nkt = 2 * qt + 2;
    const float SCL = 0.18033688011112042f;    // (1/8) * log2(e)

    const uint32_t qa = sb + (uint32_t)(w * 16 + (l & 15)) * FA_STR + (uint32_t)((l >> 4) * 8) * 2;
    const uint32_t kb_row = (uint32_t)((l & 7) + ((l >> 4) << 3)) * FA_STR
                          + (uint32_t)(((l >> 3) & 1) * 8) * 2;
    const uint32_t vb_row = (uint32_t)((l & 7) + (((l >> 3) & 1) << 3)) * FA_STR
                          + (uint32_t)((l >> 4) * 8) * 2;

    const int grow0 = qt * 128 + w * 16 + (l >> 2);   // global q row (first)
    const int cb    = (l & 3) * 2;

    for (int kt = 0; kt < nkt; kt++) {
        const int s = kt & 1;
        if (kt + 1 < nkt) {
            load_kv(kt + 1, s ^ 1);
            CPA_COMMIT();
            CPA_WAIT1();
        } else {
            CPA_WAIT0();
        }
        __syncthreads();

        if (kt == 0) {
            #pragma unroll
            for (int ks = 0; ks < 4; ks++) {
                ldsm4(qfh[ks], qa + ks * 32);
                ldsm4(qfl[ks], qa + FA_QT + ks * 32);
            }
        }

        const uint32_t Kb = sb + 2 * FA_QT + (uint32_t)s * 4 * FA_KT;
        const uint32_t Vb = Kb + 2 * FA_KT;

        // S = Q K^T (bf16x3)
        float sc[8][4] = {};
        #pragma unroll
        for (int g = 0; g < 4; g++) {
            #pragma unroll
            for (int ks = 0; ks < 4; ks++) {
                uint32_t bh[4], bl[4];
                const uint32_t ad = Kb + (uint32_t)(g * 16) * FA_STR + kb_row + ks * 32;
                ldsm4(bh, ad);
                ldsm4(bl, ad + FA_KT);
                mma_bf16(sc[2 * g],     qfh[ks], &bh[0]);
                mma_bf16(sc[2 * g],     qfh[ks], &bl[0]);
                mma_bf16(sc[2 * g],     qfl[ks], &bh[0]);
                mma_bf16(sc[2 * g + 1], qfh[ks], &bh[2]);
                mma_bf16(sc[2 * g + 1], qfh[ks], &bl[2]);
                mma_bf16(sc[2 * g + 1], qfl[ks], &bh[2]);
            }
        }

        // scale + causal mask (tiles at/after the diagonal band)
        const bool diag = (kt >= 2 * qt);
        float mx0 = -1e30f, mx1 = -1e30f;
        #pragma unroll
        for (int j = 0; j < 8; j++) {
            float s0 = sc[j][0] * SCL, s1 = sc[j][1] * SCL;
            float s2 = sc[j][2] * SCL, s3 = sc[j][3] * SCL;
            if (diag) {
                const int c = kt * 64 + j * 8 + cb;
                if (c     > grow0)     s0 = -1e30f;
                if (c + 1 > grow0)     s1 = -1e30f;
                if (c     > grow0 + 8) s2 = -1e30f;
                if (c + 1 > grow0 + 8) s3 = -1e30f;
            }
            sc[j][0] = s0; sc[j][1] = s1; sc[j][2] = s2; sc[j][3] = s3;
            mx0 = fmaxf(mx0, fmaxf(s0, s1));
            mx1 = fmaxf(mx1, fmaxf(s2, s3));
        }
        mx0 = fmaxf(mx0, __shfl_xor_sync(0xffffffffu, mx0, 1));
        mx0 = fmaxf(mx0, __shfl_xor_sync(0xffffffffu, mx0, 2));
        mx1 = fmaxf(mx1, __shfl_xor_sync(0xffffffffu, mx1, 1));
        mx1 = fmaxf(mx1, __shfl_xor_sync(0xffffffffu, mx1, 2));

        const float mn0 = fmaxf(m0, mx0);
        const float mn1 = fmaxf(m1, mx1);
        const float corr0 = ex2f(m0 - mn0);
        const float corr1 = ex2f(m1 - mn1);
        float sum0 = 0.0f, sum1 = 0.0f;
        #pragma unroll
        for (int j = 0; j < 8; j++) {
            sc[j][0] = ex2f(sc[j][0] - mn0); sum0 += sc[j][0];
            sc[j][1] = ex2f(sc[j][1] - mn0); sum0 += sc[j][1];
            sc[j][2] = ex2f(sc[j][2] - mn1); sum1 += sc[j][2];
            sc[j][3] = ex2f(sc[j][3] - mn1); sum1 += sc[j][3];
        }
        sum0 += __shfl_xor_sync(0xffffffffu, sum0, 1);
        sum0 += __shfl_xor_sync(0xffffffffu, sum0, 2);
        sum1 += __shfl_xor_sync(0xffffffffu, sum1, 1);
        sum1 += __shfl_xor_sync(0xffffffffu, sum1, 2);
        l0 = l0 * corr0 + sum0;
        l1 = l1 * corr1 + sum1;
        m0 = mn0; m1 = mn1;

        #pragma unroll
        for (int j = 0; j < 8; j++) {
            o[j][0] *= corr0; o[j][1] *= corr0;
            o[j][2] *= corr1; o[j][3] *= corr1;
        }

        // P fragments (hi/lo) from S accumulators
        uint32_t pah[4][4], pal[4][4];
        #pragma unroll
        for (int ks = 0; ks < 4; ks++) {
            pah[ks][0] = pack_hi(sc[2 * ks][0],     sc[2 * ks][1]);
            pal[ks][0] = pack_lo(sc[2 * ks][0],     sc[2 * ks][1]);
            pah[ks][1] = pack_hi(sc[2 * ks][2],     sc[2 * ks][3]);
            pal[ks][1] = pack_lo(sc[2 * ks][2],     sc[2 * ks][3]);
            pah[ks][2] = pack_hi(sc[2 * ks + 1][0], sc[2 * ks + 1][1]);
            pal[ks][2] = pack_lo(sc[2 * ks + 1][0], sc[2 * ks + 1][1]);
            pah[ks][3] = pack_hi(sc[2 * ks + 1][2], sc[2 * ks + 1][3]);
            pal[ks][3] = pack_lo(sc[2 * ks + 1][2], sc[2 * ks + 1][3]);
        }

        // O += P V (bf16x3), V via ldmatrix.trans
        #pragma unroll
        for (int g = 0; g < 4; g++) {
            #pragma unroll
            for (int ks = 0; ks < 4; ks++) {
                uint32_t vh[4], vl[4];
                const uint32_t ad = Vb + (uint32_t)(ks * 16) * FA_STR + vb_row + g * 32;
                ldsm4t(vh, ad);
                ldsm4t(vl, ad + FA_KT);
                mma_bf16(o[2 * g],     pah[ks], &vh[0]);
                mma_bf16(o[2 * g],     pah[ks], &vl[0]);
                mma_bf16(o[2 * g],     pal[ks], &vh[0]);
                mma_bf16(o[2 * g + 1], pah[ks], &vh[2]);
                mma_bf16(o[2 * g + 1], pah[ks], &vl[2]);
                mma_bf16(o[2 * g + 1], pal[ks], &vh[2]);
            }
        }
        __syncthreads();
    }

    // Epilogue: normalize + write hi/lo bf16
    const float i0 = 1.0f / l0;
    const float i1 = 1.0f / l1;
    const size_t row0 = (size_t)(b * TT + qt * 128 + w * 16 + (l >> 2));
    const size_t row1 = row0 + 8;
    const int colb = h * HD + cb;
    #pragma unroll
    for (int j = 0; j < 8; j++) {
        const size_t c = colb + j * 8;
        const float v0 = o[j][0] * i0, v1 = o[j][1] * i0;
        const float v2 = o[j][2] * i1, v3 = o[j][3] * i1;
        *(uint32_t*)&oh[row0 * HH + c] = pack_hi(v0, v1);
        *(uint32_t*)&ol[row0 * HH + c] = pack_lo(v0, v1);
        *(uint32_t*)&oh[row1 * HH + c] = pack_hi(v2, v3);
        *(uint32_t*)&ol[row1 * HH + c] = pack_lo(v2, v3);
    }
}

// ---------------------------------------------------------------------------
extern "C" void kernel_launch(void* const* d_in, const int* in_sizes, int n_in,
                              void* d_out, int out_size) {
    const float* x    = (const float*)d_in[0];   // [4,2048,1024]
    const float* Wqkv = (const float*)d_in[1];   // [3072,1024]
    const float* Wout = (const float*)d_in[2];   // [1024,1024]
    float* out = (float*)d_out;                  // [4,2048,1024]

    __nv_bfloat16 *qh, *ql, *xhi, *xlo, *wqh, *wql, *woh, *wol, *ahi, *alo;
    cudaGetSymbolAddress((void**)&qh,  g_qkv_hi);
    cudaGetSymbolAddress((void**)&ql,  g_qkv_lo);
    cudaGetSymbolAddress((void**)&xhi, g_x_hi);
    cudaGetSymbolAddress((void**)&xlo, g_x_lo);
    cudaGetSymbolAddress((void**)&wqh, g_wqkv_hi);
    cudaGetSymbolAddress((void**)&wql, g_wqkv_lo);
    cudaGetSymbolAddress((void**)&woh, g_wout_hi);
    cudaGetSymbolAddress((void**)&wol, g_wout_lo);
    cudaGetSymbolAddress((void**)&ahi, g_attn_hi);
    cudaGetSymbolAddress((void**)&alo, g_attn_lo);

    cudaFuncSetAttribute(gemm_hmma<true>,  cudaFuncAttributeMaxDynamicSharedMemorySize, 2 * STAGE_B);
    cudaFuncSetAttribute(gemm_hmma<false>, cudaFuncAttributeMaxDynamicSharedMemorySize, 2 * STAGE_B);
    cudaFuncSetAttribute(flash_tc, cudaFuncAttributeMaxDynamicSharedMemorySize, FA_SMEM);

    // Split inputs into bf16 hi/lo
    {
        int n1 = ROWS * HH;
        split_bf16<<<(n1 / 4 + 255) / 256, 256>>>(x, xhi, xlo, n1);
        int n2 = QKV_COLS * HH;
        split_bf16<<<(n2 / 4 + 255) / 256, 256>>>(Wqkv, wqh, wql, n2);
        int n3 = HH * HH;
        split_bf16<<<(n3 / 4 + 255) / 256, 256>>>(Wout, woh, wol, n3);
    }

    // 1) qkv = x @ W_qkv^T -> bf16 hi/lo directly
    gemm_hmma<true><<<dim3(QKV_COLS / 128, ROWS / 128), 256, 2 * STAGE_B>>>(
        xhi, xlo, wqh, wql, nullptr, qh, ql, ROWS, QKV_COLS, HH);

    // 2) tensor-core causal flash attention (128-row q-tiles) -> bf16 hi/lo
    flash_tc<<<dim3(TT / 128, NH, BB), 256, FA_SMEM>>>(qh, ql, ahi, alo);

    // 3) out = attn @ W_out^T -> fp32
    gemm_hmma<false><<<dim3(HH / 128, ROWS / 128), 256, 2 * STAGE_B>>>(
        ahi, alo, woh, wol, out, nullptr, nullptr, ROWS, HH, HH);
}

// round 8
// speedup vs baseline: 2.7061x; 1.0285x over previous
#include <cuda_runtime.h>
#include <cuda_bf16.h>
#include <cstdint>

// Problem constants
#define BB 4
#define TT 2048
#define HH 1024
#define NH 16
#define HD 64
#define ROWS (BB*TT)          // 8192
#define QKV_COLS (3*HH)       // 3072

// Scratch (device globals; no runtime allocation allowed)
__device__ __nv_bfloat16 g_qkv_hi[(size_t)ROWS * QKV_COLS];
__device__ __nv_bfloat16 g_qkv_lo[(size_t)ROWS * QKV_COLS];
__device__ __nv_bfloat16 g_x_hi[(size_t)ROWS * HH];
__device__ __nv_bfloat16 g_x_lo[(size_t)ROWS * HH];
__device__ __nv_bfloat16 g_wqkv_hi[(size_t)QKV_COLS * HH];
__device__ __nv_bfloat16 g_wqkv_lo[(size_t)QKV_COLS * HH];
__device__ __nv_bfloat16 g_wout_hi[(size_t)HH * HH];
__device__ __nv_bfloat16 g_wout_lo[(size_t)HH * HH];
__device__ __nv_bfloat16 g_attn_hi[(size_t)ROWS * HH];
__device__ __nv_bfloat16 g_attn_lo[(size_t)ROWS * HH];

// ---------------------------------------------------------------------------
// Helpers
// ---------------------------------------------------------------------------
__device__ __forceinline__ uint32_t smem_u32_of(const void* p) {
    uint32_t a;
    asm("{ .reg .u64 t; cvta.to.shared.u64 t, %1; cvt.u32.u64 %0, t; }"
        : "=r"(a) : "l"(p));
    return a;
}

#define CPA16(dst, src) \
    asm volatile("cp.async.cg.shared.global [%0], [%1], 16;" :: "r"(dst), "l"(src))
#define CPA_COMMIT() asm volatile("cp.async.commit_group;" ::: "memory")
#define CPA_WAIT1()  asm volatile("cp.async.wait_group 1;" ::: "memory")
#define CPA_WAIT0()  asm volatile("cp.async.wait_group 0;" ::: "memory")

__device__ __forceinline__ void ldsm4(uint32_t* r, uint32_t addr) {
    asm volatile("ldmatrix.sync.aligned.m8n8.x4.shared.b16 {%0,%1,%2,%3}, [%4];"
                 : "=r"(r[0]), "=r"(r[1]), "=r"(r[2]), "=r"(r[3]) : "r"(addr));
}
__device__ __forceinline__ void ldsm4t(uint32_t* r, uint32_t addr) {
    asm volatile("ldmatrix.sync.aligned.m8n8.x4.trans.shared.b16 {%0,%1,%2,%3}, [%4];"
                 : "=r"(r[0]), "=r"(r[1]), "=r"(r[2]), "=r"(r[3]) : "r"(addr));
}

__device__ __forceinline__ void mma_bf16(float* c, const uint32_t* a, const uint32_t* b) {
    asm volatile(
        "mma.sync.aligned.m16n8k16.row.col.f32.bf16.bf16.f32 "
        "{%0,%1,%2,%3}, {%4,%5,%6,%7}, {%8,%9}, {%0,%1,%2,%3};"
        : "+f"(c[0]), "+f"(c[1]), "+f"(c[2]), "+f"(c[3])
        : "r"(a[0]), "r"(a[1]), "r"(a[2]), "r"(a[3]), "r"(b[0]), "r"(b[1]));
}

__device__ __forceinline__ float ex2f(float x) {
    float y;
    asm("ex2.approx.ftz.f32 %0, %1;" : "=f"(y) : "f"(x));
    return y;
}

__device__ __forceinline__ uint32_t pack_hi(float a, float b) {
    __nv_bfloat162 v(__float2bfloat16(a), __float2bfloat16(b));
    return *(uint32_t*)&v;
}
__device__ __forceinline__ uint32_t pack_lo(float a, float b) {
    __nv_bfloat16 ha = __float2bfloat16(a), hb = __float2bfloat16(b);
    __nv_bfloat162 v(__float2bfloat16(a - __bfloat162float(ha)),
                     __float2bfloat16(b - __bfloat162float(hb)));
    return *(uint32_t*)&v;
}

// ---------------------------------------------------------------------------
// fp32 -> bf16 hi/lo split
// ---------------------------------------------------------------------------
__global__ __launch_bounds__(256) void split_bf16(const float* __restrict__ src,
                                                  __nv_bfloat16* __restrict__ hi,
                                                  __nv_bfloat16* __restrict__ lo,
                                                  int n) {
    int i = (blockIdx.x * blockDim.x + threadIdx.x) * 4;
    if (i >= n) return;
    float4 v = *(const float4*)(src + i);
    float f[4] = {v.x, v.y, v.z, v.w};
    __nv_bfloat16 h[4], l[4];
    #pragma unroll
    for (int j = 0; j < 4; j++) {
        h[j] = __float2bfloat16(f[j]);
        l[j] = __float2bfloat16(f[j] - __bfloat162float(h[j]));
    }
    *(__nv_bfloat162*)(hi + i)     = __nv_bfloat162(h[0], h[1]);
    *(__nv_bfloat162*)(hi + i + 2) = __nv_bfloat162(h[2], h[3]);
    *(__nv_bfloat162*)(lo + i)     = __nv_bfloat162(l[0], l[1]);
    *(__nv_bfloat162*)(lo + i + 2) = __nv_bfloat162(l[2], l[3]);
}

// ---------------------------------------------------------------------------
// bf16x3 HMMA GEMM (NT): C = (Ahi+Alo) * (Bhi+Blo)^T, fp32 accum.
// 3-stage swizzled pipeline, ONE __syncthreads per K-chunk, prefetch depth 2.
// Smem tile: 128 rows x 64B (KC=32 bf16), 16B-chunk XOR swizzle (c4 ^= row&3).
// ---------------------------------------------------------------------------
#define KC 32
#define TILE2_B (128 * 64)          // 8192 B per tensor tile
#define STAGE2_B (4 * TILE2_B)      // 32768 B (Ah, Al, Bh, Bl)
#define GSMEM (3 * STAGE2_B)        // 98304 B, 3 stages

__device__ __forceinline__ uint32_t gsw(uint32_t row, uint32_t c4) {
    return row * 64u + ((c4 ^ (row & 3u)) << 4);
}

template <bool SPLIT>
__global__ __launch_bounds__(256) void gemm_hmma(
    const __nv_bfloat16* __restrict__ Ahi, const __nv_bfloat16* __restrict__ Alo,
    const __nv_bfloat16* __restrict__ Bhi, const __nv_bfloat16* __restrict__ Blo,
    float* __restrict__ C, __nv_bfloat16* __restrict__ Chi,
    __nv_bfloat16* __restrict__ Clo, int M, int N, int K) {
    extern __shared__ char sm[];
    const uint32_t sbase = smem_u32_of(sm);

    const int tid  = threadIdx.x;
    const int wid  = tid >> 5;
    const int lane = tid & 31;
    const int m0 = blockIdx.y * 128;
    const int n0 = blockIdx.x * 128;
    const int wm = wid >> 2;
    const int wn = wid & 3;

    // Loader: thread -> (row = tid>>1, two 16B chunks)
    const int lrow = tid >> 1;
    const int lc0  = (tid & 1) * 2;
    const __nv_bfloat16* gAh = Ahi + (size_t)(m0 + lrow) * K;
    const __nv_bfloat16* gAl = Alo + (size_t)(m0 + lrow) * K;
    const __nv_bfloat16* gBh = Bhi + (size_t)(n0 + lrow) * K;
    const __nv_bfloat16* gBl = Blo + (size_t)(n0 + lrow) * K;

    float acc[4][4][4] = {};
    const int NCH = K / KC;

    auto load_stage = [&](int c, int s) {
        const uint32_t st = sbase + (uint32_t)s * STAGE2_B;
        #pragma unroll
        for (int j = 0; j < 2; j++) {
            const uint32_t c4 = (uint32_t)(lc0 + j);
            const uint32_t dof = gsw((uint32_t)lrow, c4);
            const size_t go = (size_t)c * KC + c4 * 8;
            CPA16(st + dof,               gAh + go);
            CPA16(st + TILE2_B + dof,     gAl + go);
            CPA16(st + 2 * TILE2_B + dof, gBh + go);
            CPA16(st + 3 * TILE2_B + dof, gBl + go);
        }
    };

    load_stage(0, 0);
    CPA_COMMIT();
    load_stage(1, 1);
    CPA_COMMIT();

    const int arow = wm * 64 + (lane & 15);          // A row within 128-tile
    const uint32_t ac4b = (uint32_t)(lane >> 4);     // A 16B-chunk sub-index
    const int brow = wn * 32 + (lane & 7) + ((lane >> 4) << 3);  // B row (n)
    const uint32_t bc4b = (uint32_t)((lane >> 3) & 1);

    for (int c = 0; c < NCH; c++) {
        if (c + 1 < NCH) CPA_WAIT1(); else CPA_WAIT0();
        __syncthreads();
        if (c + 2 < NCH) {
            load_stage(c + 2, (c + 2) % 3);
            CPA_COMMIT();
        }

        const uint32_t Ah_b = sbase + (uint32_t)(c % 3) * STAGE2_B;
        const uint32_t Al_b = Ah_b + TILE2_B;
        const uint32_t Bh_b = Ah_b + 2 * TILE2_B;
        const uint32_t Bl_b = Ah_b + 3 * TILE2_B;

        #pragma unroll
        for (int ks = 0; ks < 2; ks++) {
            const uint32_t ac4 = (uint32_t)(ks * 2) + ac4b;
            const uint32_t bc4 = (uint32_t)(ks * 2) + bc4b;
            uint32_t bh[2][4], bl[2][4];
            #pragma unroll
            for (int nj2 = 0; nj2 < 2; nj2++) {
                const uint32_t boff = gsw((uint32_t)(brow + nj2 * 16), bc4);
                ldsm4(bh[nj2], Bh_b + boff);
                ldsm4(bl[nj2], Bl_b + boff);
            }
            uint32_t ah[4][4], al[4][4];
            #pragma unroll
            for (int mi = 0; mi < 4; mi++) {
                const uint32_t aoff = gsw((uint32_t)(arow + mi * 16), ac4);
                ldsm4(ah[mi], Ah_b + aoff);
                ldsm4(al[mi], Al_b + aoff);
            }
            #pragma unroll
            for (int nj2 = 0; nj2 < 2; nj2++) {
                #pragma unroll
                for (int mi = 0; mi < 4; mi++) {
                    #pragma unroll
                    for (int j = 0; j < 2; j++) {
                        float* a4 = acc[mi][nj2 * 2 + j];
                        mma_bf16(a4, ah[mi], &bh[nj2][2 * j]);
                        mma_bf16(a4, ah[mi], &bl[nj2][2 * j]);
                        mma_bf16(a4, al[mi], &bh[nj2][2 * j]);
                    }
                }
            }
        }
    }

    const int gr = lane >> 2;
    const int gc = (lane & 3) * 2;
    #pragma unroll
    for (int mi = 0; mi < 4; mi++) {
        #pragma unroll
        for (int nj = 0; nj < 4; nj++) {
            const int row = m0 + wm * 64 + mi * 16 + gr;
            const int col = n0 + wn * 32 + nj * 8 + gc;
            if (SPLIT) {
                *(uint32_t*)&Chi[(size_t)row * N + col] = pack_hi(acc[mi][nj][0], acc[mi][nj][1]);
                *(uint32_t*)&Clo[(size_t)row * N + col] = pack_lo(acc[mi][nj][0], acc[mi][nj][1]);
                *(uint32_t*)&Chi[(size_t)(row + 8) * N + col] = pack_hi(acc[mi][nj][2], acc[mi][nj][3]);
                *(uint32_t*)&Clo[(size_t)(row + 8) * N + col] = pack_lo(acc[mi][nj][2], acc[mi][nj][3]);
            } else {
                *(float2*)&C[(size_t)row * N + col] =
                    make_float2(acc[mi][nj][0], acc[mi][nj][1]);
                *(float2*)&C[(size_t)(row + 8) * N + col] =
                    make_float2(acc[mi][nj][2], acc[mi][nj][3]);
            }
        }
    }
}

// ---------------------------------------------------------------------------
// Tensor-core causal flash attention (bf16x3 both MMAs).
// One CTA = (128-row q-tile, head, batch), 8 warps, k-tiles of 64,
// double-buffered K/V via cp.async, ONE __syncthreads per k-tile.
// ---------------------------------------------------------------------------
#define FA_STR 144                  // bytes per smem row (64 bf16 + 8 pad)
#define FA_QT  (128 * FA_STR)       // 18432  (Q tile: 128 rows)
#define FA_KT  (64 * FA_STR)        // 9216   (K/V tile: 64 rows)
#define FA_SMEM (2 * FA_QT + 2 * 4 * FA_KT)   // 110592

__global__ __launch_bounds__(256) void flash_tc(
    const __nv_bfloat16* __restrict__ qkh, const __nv_bfloat16* __restrict__ qkl,
    __nv_bfloat16* __restrict__ oh, __nv_bfloat16* __restrict__ ol) {
    extern __shared__ char sm[];
    const uint32_t sb = smem_u32_of(sm);
    const int qt = (int)gridDim.x - 1 - (int)blockIdx.x;   // long tiles first
    const int h  = blockIdx.y;
    const int b  = blockIdx.z;
    const int tid = threadIdx.x;
    const int w = tid >> 5;
    const int l = tid & 31;

    // Q load: 128 rows, thread -> (row = tid>>1, 64B half)
    {
        const int r  = tid >> 1;
        const int hf = tid & 1;
        const size_t qoff = ((size_t)(b * TT + qt * 128 + r)) * QKV_COLS + h * HD + hf * 32;
        const uint32_t d0 = sb + (uint32_t)r * FA_STR + (uint32_t)hf * 64;
        #pragma unroll
        for (int i = 0; i < 4; i++) {
            CPA16(d0 + 16 * i,         qkh + qoff + 8 * i);
            CPA16(d0 + FA_QT + 16 * i, qkl + qoff + 8 * i);
        }
    }

    // K/V load: 64 rows, thread -> (row = tid>>2, 32B quarter)
    const int kr = tid >> 2;
    const int kq = tid & 3;
    auto load_kv = [&](int kt, int s) {
        const size_t koff = ((size_t)(b * TT + kt * 64 + kr)) * QKV_COLS + HH + h * HD + kq * 16;
        const size_t voff = koff + HH;
        const uint32_t d = sb + 2 * FA_QT + (uint32_t)s * 4 * FA_KT
                         + (uint32_t)kr * FA_STR + (uint32_t)kq * 32;
        CPA16(d,                 qkh + koff);
        CPA16(d + 16,            qkh + koff + 8);
        CPA16(d + FA_KT,         qkl + koff);
        CPA16(d + FA_KT + 16,    qkl + koff + 8);
        CPA16(d + 2 * FA_KT,      qkh + voff);
        CPA16(d + 2 * FA_KT + 16, qkh + voff + 8);
        CPA16(d + 3 * FA_KT,      qkl + voff);
        CPA16(d + 3 * FA_KT + 16, qkl + voff + 8);
    };

    load_kv(0, 0);
    CPA_COMMIT();

    float o[8][4] = {};
    float m0 = -1e30f, m1 = -1e30f, l0 = 0.0f, l1 = 0.0f;
    uint32_t qfh[4][4], qfl[4][4];
    const int nkt = 2 * qt + 2;
    const float SCL = 0.18033688011112042f;    // (1/8) * log2(e)

    const uint32_t qa = sb + (uint32_t)(w * 16 + (l & 15)) * FA_STR + (uint32_t)((l >> 4) * 8) * 2;
    const uint32_t kb_row = (uint32_t)((l & 7) + ((l >> 4) << 3)) * FA_STR
                          + (uint32_t)(((l >> 3) & 1) * 8) * 2;
    const uint32_t vb_row = (uint32_t)((l & 7) + (((l >> 3) & 1) << 3)) * FA_STR
                          + (uint32_t)((l >> 4) * 8) * 2;

    const int grow0 = qt * 128 + w * 16 + (l >> 2);   // global q row (first)
    const int cb    = (l & 3) * 2;

    for (int kt = 0; kt < nkt; kt++) {
        const int s = kt & 1;
        CPA_WAIT0();            // tile kt (sole group in flight) complete
        __syncthreads();        // visibility + WAR separation (single barrier)
        if (kt + 1 < nkt) {
            load_kv(kt + 1, s ^ 1);   // streams during this tile's MMAs
            CPA_COMMIT();
        }

        if (kt == 0) {
            #pragma unroll
            for (int ks = 0; ks < 4; ks++) {
                ldsm4(qfh[ks], qa + ks * 32);
                ldsm4(qfl[ks], qa + FA_QT + ks * 32);
            }
        }

        const uint32_t Kb = sb + 2 * FA_QT + (uint32_t)s * 4 * FA_KT;
        const uint32_t Vb = Kb + 2 * FA_KT;

        // S = Q K^T (bf16x3)
        float sc[8][4] = {};
        #pragma unroll
        for (int g = 0; g < 4; g++) {
            #pragma unroll
            for (int ks = 0; ks < 4; ks++) {
                uint32_t bh[4], bl[4];
                const uint32_t ad = Kb + (uint32_t)(g * 16) * FA_STR + kb_row + ks * 32;
                ldsm4(bh, ad);
                ldsm4(bl, ad + FA_KT);
                mma_bf16(sc[2 * g],     qfh[ks], &bh[0]);
                mma_bf16(sc[2 * g],     qfh[ks], &bl[0]);
                mma_bf16(sc[2 * g],     qfl[ks], &bh[0]);
                mma_bf16(sc[2 * g + 1], qfh[ks], &bh[2]);
                mma_bf16(sc[2 * g + 1], qfh[ks], &bl[2]);
                mma_bf16(sc[2 * g + 1], qfl[ks], &bh[2]);
            }
        }

        // scale + causal mask (tiles at/after the diagonal band)
        const bool diag = (kt >= 2 * qt);
        float mx0 = -1e30f, mx1 = -1e30f;
        #pragma unroll
        for (int j = 0; j < 8; j++) {
            float s0 = sc[j][0] * SCL, s1 = sc[j][1] * SCL;
            float s2 = sc[j][2] * SCL, s3 = sc[j][3] * SCL;
            if (diag) {
                const int c = kt * 64 + j * 8 + cb;
                if (c     > grow0)     s0 = -1e30f;
                if (c + 1 > grow0)     s1 = -1e30f;
                if (c     > grow0 + 8) s2 = -1e30f;
                if (c + 1 > grow0 + 8) s3 = -1e30f;
            }
            sc[j][0] = s0; sc[j][1] = s1; sc[j][2] = s2; sc[j][3] = s3;
            mx0 = fmaxf(mx0, fmaxf(s0, s1));
            mx1 = fmaxf(mx1, fmaxf(s2, s3));
        }
        mx0 = fmaxf(mx0, __shfl_xor_sync(0xffffffffu, mx0, 1));
        mx0 = fmaxf(mx0, __shfl_xor_sync(0xffffffffu, mx0, 2));
        mx1 = fmaxf(mx1, __shfl_xor_sync(0xffffffffu, mx1, 1));
        mx1 = fmaxf(mx1, __shfl_xor_sync(0xffffffffu, mx1, 2));

        const float mn0 = fmaxf(m0, mx0);
        const float mn1 = fmaxf(m1, mx1);
        const float corr0 = ex2f(m0 - mn0);
        const float corr1 = ex2f(m1 - mn1);
        float sum0 = 0.0f, sum1 = 0.0f;
        #pragma unroll
        for (int j = 0; j < 8; j++) {
            sc[j][0] = ex2f(sc[j][0] - mn0); sum0 += sc[j][0];
            sc[j][1] = ex2f(sc[j][1] - mn0); sum0 += sc[j][1];
            sc[j][2] = ex2f(sc[j][2] - mn1); sum1 += sc[j][2];
            sc[j][3] = ex2f(sc[j][3] - mn1); sum1 += sc[j][3];
        }
        sum0 += __shfl_xor_sync(0xffffffffu, sum0, 1);
        sum0 += __shfl_xor_sync(0xffffffffu, sum0, 2);
        sum1 += __shfl_xor_sync(0xffffffffu, sum1, 1);
        sum1 += __shfl_xor_sync(0xffffffffu, sum1, 2);
        l0 = l0 * corr0 + sum0;
        l1 = l1 * corr1 + sum1;
        m0 = mn0; m1 = mn1;

        #pragma unroll
        for (int j = 0; j < 8; j++) {
            o[j][0] *= corr0; o[j][1] *= corr0;
            o[j][2] *= corr1; o[j][3] *= corr1;
        }

        // P fragments (hi/lo) from S accumulators
        uint32_t pah[4][4], pal[4][4];
        #pragma unroll
        for (int ks = 0; ks < 4; ks++) {
            pah[ks][0] = pack_hi(sc[2 * ks][0],     sc[2 * ks][1]);
            pal[ks][0] = pack_lo(sc[2 * ks][0],     sc[2 * ks][1]);
            pah[ks][1] = pack_hi(sc[2 * ks][2],     sc[2 * ks][3]);
            pal[ks][1] = pack_lo(sc[2 * ks][2],     sc[2 * ks][3]);
            pah[ks][2] = pack_hi(sc[2 * ks + 1][0], sc[2 * ks + 1][1]);
            pal[ks][2] = pack_lo(sc[2 * ks + 1][0], sc[2 * ks + 1][1]);
            pah[ks][3] = pack_hi(sc[2 * ks + 1][2], sc[2 * ks + 1][3]);
            pal[ks][3] = pack_lo(sc[2 * ks + 1][2], sc[2 * ks + 1][3]);
        }

        // O += P V (bf16x3), V via ldmatrix.trans
        #pragma unroll
        for (int g = 0; g < 4; g++) {
            #pragma unroll
            for (int ks = 0; ks < 4; ks++) {
                uint32_t vh[4], vl[4];
                const uint32_t ad = Vb + (uint32_t)(ks * 16) * FA_STR + vb_row + g * 32;
                ldsm4t(vh, ad);
                ldsm4t(vl, ad + FA_KT);
                mma_bf16(o[2 * g],     pah[ks], &vh[0]);
                mma_bf16(o[2 * g],     pah[ks], &vl[0]);
                mma_bf16(o[2 * g],     pal[ks], &vh[0]);
                mma_bf16(o[2 * g + 1], pah[ks], &vh[2]);
                mma_bf16(o[2 * g + 1], pah[ks], &vl[2]);
                mma_bf16(o[2 * g + 1], pal[ks], &vh[2]);
            }
        }
    }

    // Epilogue: normalize + write hi/lo bf16 (registers only; no smem use)
    const float i0 = 1.0f / l0;
    const float i1 = 1.0f / l1;
    const size_t row0 = (size_t)(b * TT + qt * 128 + w * 16 + (l >> 2));
    const size_t row1 = row0 + 8;
    const int colb = h * HD + cb;
    #pragma unroll
    for (int j = 0; j < 8; j++) {
        const size_t c = colb + j * 8;
        const float v0 = o[j][0] * i0, v1 = o[j][1] * i0;
        const float v2 = o[j][2] * i1, v3 = o[j][3] * i1;
        *(uint32_t*)&oh[row0 * HH + c] = pack_hi(v0, v1);
        *(uint32_t*)&ol[row0 * HH + c] = pack_lo(v0, v1);
        *(uint32_t*)&oh[row1 * HH + c] = pack_hi(v2, v3);
        *(uint32_t*)&ol[row1 * HH + c] = pack_lo(v2, v3);
    }
}

// ---------------------------------------------------------------------------
extern "C" void kernel_launch(void* const* d_in, const int* in_sizes, int n_in,
                              void* d_out, int out_size) {
    const float* x    = (const float*)d_in[0];   // [4,2048,1024]
    const float* Wqkv = (const float*)d_in[1];   // [3072,1024]
    const float* Wout = (const float*)d_in[2];   // [1024,1024]
    float* out = (float*)d_out;                  // [4,2048,1024]

    __nv_bfloat16 *qh, *ql, *xhi, *xlo, *wqh, *wql, *woh, *wol, *ahi, *alo;
    cudaGetSymbolAddress((void**)&qh,  g_qkv_hi);
    cudaGetSymbolAddress((void**)&ql,  g_qkv_lo);
    cudaGetSymbolAddress((void**)&xhi, g_x_hi);
    cudaGetSymbolAddress((void**)&xlo, g_x_lo);
    cudaGetSymbolAddress((void**)&wqh, g_wqkv_hi);
    cudaGetSymbolAddress((void**)&wql, g_wqkv_lo);
    cudaGetSymbolAddress((void**)&woh, g_wout_hi);
    cudaGetSymbolAddress((void**)&wol, g_wout_lo);
    cudaGetSymbolAddress((void**)&ahi, g_attn_hi);
    cudaGetSymbolAddress((void**)&alo, g_attn_lo);

    cudaFuncSetAttribute(gemm_hmma<true>,  cudaFuncAttributeMaxDynamicSharedMemorySize, GSMEM);
    cudaFuncSetAttribute(gemm_hmma<false>, cudaFuncAttributeMaxDynamicSharedMemorySize, GSMEM);
    cudaFuncSetAttribute(flash_tc, cudaFuncAttributeMaxDynamicSharedMemorySize, FA_SMEM);

    // Split inputs into bf16 hi/lo
    {
        int n1 = ROWS * HH;
        split_bf16<<<(n1 / 4 + 255) / 256, 256>>>(x, xhi, xlo, n1);
        int n2 = QKV_COLS * HH;
        split_bf16<<<(n2 / 4 + 255) / 256, 256>>>(Wqkv, wqh, wql, n2);
        int n3 = HH * HH;
        split_bf16<<<(n3 / 4 + 255) / 256, 256>>>(Wout, woh, wol, n3);
    }

    // 1) qkv = x @ W_qkv^T -> bf16 hi/lo directly
    gemm_hmma<true><<<dim3(QKV_COLS / 128, ROWS / 128), 256, GSMEM>>>(
        xhi, xlo, wqh, wql, nullptr, qh, ql, ROWS, QKV_COLS, HH);

    // 2) tensor-core causal flash attention (128-row q-tiles) -> bf16 hi/lo
    flash_tc<<<dim3(TT / 128, NH, BB), 256, FA_SMEM>>>(qh, ql, ahi, alo);

    // 3) out = attn @ W_out^T -> fp32
    gemm_hmma<false><<<dim3(HH / 128, ROWS / 128), 256, GSMEM>>>(
        ahi, alo, woh, wol, out, nullptr, nullptr, ROWS, HH, HH);
}

// round 9
// speedup vs baseline: 3.5646x; 1.3172x over previous
#include <cuda_runtime.h>
#include <cuda_fp16.h>
#include <cstdint>

// Problem constants
#define BB 4
#define TT 2048
#define HH 1024
#define NH 16
#define HD 64
#define ROWS (BB*TT)          // 8192
#define QKV_COLS (3*HH)       // 3072

// Scratch (device globals; no runtime allocation allowed)
__device__ __half g_qkv_hi[(size_t)ROWS * QKV_COLS];
__device__ __half g_qkv_lo[(size_t)ROWS * QKV_COLS];
__device__ __half g_x_hi[(size_t)ROWS * HH];
__device__ __half g_x_lo[(size_t)ROWS * HH];
__device__ __half g_wqkv_hi[(size_t)QKV_COLS * HH];
__device__ __half g_wout_hi[(size_t)HH * HH];
__device__ __half g_attn_hi[(size_t)ROWS * HH];
__device__ __half g_attn_lo[(size_t)ROWS * HH];

// ---------------------------------------------------------------------------
// Helpers
// ---------------------------------------------------------------------------
__device__ __forceinline__ uint32_t smem_u32_of(const void* p) {
    uint32_t a;
    asm("{ .reg .u64 t; cvta.to.shared.u64 t, %1; cvt.u32.u64 %0, t; }"
        : "=r"(a) : "l"(p));
    return a;
}

#define CPA16(dst, src) \
    asm volatile("cp.async.cg.shared.global [%0], [%1], 16;" :: "r"(dst), "l"(src))
#define CPA_COMMIT() asm volatile("cp.async.commit_group;" ::: "memory")
#define CPA_WAIT1()  asm volatile("cp.async.wait_group 1;" ::: "memory")
#define CPA_WAIT0()  asm volatile("cp.async.wait_group 0;" ::: "memory")

__device__ __forceinline__ void ldsm4(uint32_t* r, uint32_t addr) {
    asm volatile("ldmatrix.sync.aligned.m8n8.x4.shared.b16 {%0,%1,%2,%3}, [%4];"
                 : "=r"(r[0]), "=r"(r[1]), "=r"(r[2]), "=r"(r[3]) : "r"(addr));
}
__device__ __forceinline__ void ldsm4t(uint32_t* r, uint32_t addr) {
    asm volatile("ldmatrix.sync.aligned.m8n8.x4.trans.shared.b16 {%0,%1,%2,%3}, [%4];"
                 : "=r"(r[0]), "=r"(r[1]), "=r"(r[2]), "=r"(r[3]) : "r"(addr));
}

__device__ __forceinline__ void mma_f16(float* c, const uint32_t* a, const uint32_t* b) {
    asm volatile(
        "mma.sync.aligned.m16n8k16.row.col.f32.f16.f16.f32 "
        "{%0,%1,%2,%3}, {%4,%5,%6,%7}, {%8,%9}, {%0,%1,%2,%3};"
        : "+f"(c[0]), "+f"(c[1]), "+f"(c[2]), "+f"(c[3])
        : "r"(a[0]), "r"(a[1]), "r"(a[2]), "r"(a[3]), "r"(b[0]), "r"(b[1]));
}

__device__ __forceinline__ float ex2f(float x) {
    float y;
    asm("ex2.approx.ftz.f32 %0, %1;" : "=f"(y) : "f"(x));
    return y;
}

__device__ __forceinline__ uint32_t pack2h(float a, float b) {
    __half2 v(__float2half(a), __float2half(b));
    return *(uint32_t*)&v;
}
__device__ __forceinline__ uint32_t pack2h_lo(float a, float b) {
    __half ha = __float2half(a), hb = __float2half(b);
    __half2 v(__float2half(a - __half2float(ha)),
              __float2half(b - __half2float(hb)));
    return *(uint32_t*)&v;
}

// ---------------------------------------------------------------------------
// fp32 -> fp16 hi/lo split, and hi-only convert (for weights)
// ---------------------------------------------------------------------------
__global__ __launch_bounds__(256) void split_f16(const float* __restrict__ src,
                                                 __half* __restrict__ hi,
                                                 __half* __restrict__ lo,
                                                 int n) {
    int i = (blockIdx.x * blockDim.x + threadIdx.x) * 4;
    if (i >= n) return;
    float4 v = *(const float4*)(src + i);
    *(uint32_t*)(hi + i)     = pack2h(v.x, v.y);
    *(uint32_t*)(hi + i + 2) = pack2h(v.z, v.w);
    *(uint32_t*)(lo + i)     = pack2h_lo(v.x, v.y);
    *(uint32_t*)(lo + i + 2) = pack2h_lo(v.z, v.w);
}

__global__ __launch_bounds__(256) void conv_f16(const float* __restrict__ src,
                                                __half* __restrict__ hi, int n) {
    int i = (blockIdx.x * blockDim.x + threadIdx.x) * 4;
    if (i >= n) return;
    float4 v = *(const float4*)(src + i);
    *(uint32_t*)(hi + i)     = pack2h(v.x, v.y);
    *(uint32_t*)(hi + i + 2) = pack2h(v.z, v.w);
}

// ---------------------------------------------------------------------------
// fp16x2 HMMA GEMM (NT): C = (Ahi+Alo) * Bhi^T, fp32 accum.
// A kept to 22 bits (hi+lo), B fp16-rounded (~2^-12 rel err).
// 3-stage swizzled pipeline, one __syncthreads per K-chunk, prefetch depth 2.
// ---------------------------------------------------------------------------
#define KC 32
#define TILE2_B (128 * 64)          // 8192 B per tensor tile
#define STAGE2_B (3 * TILE2_B)      // 24576 B (Ah, Al, Bh)
#define GSMEM (3 * STAGE2_B)        // 73728 B, 3 stages

__device__ __forceinline__ uint32_t gsw(uint32_t row, uint32_t c4) {
    return row * 64u + ((c4 ^ (row & 3u)) << 4);
}

template <bool SPLIT>
__global__ __launch_bounds__(256) void gemm_hmma(
    const __half* __restrict__ Ahi, const __half* __restrict__ Alo,
    const __half* __restrict__ Bhi,
    float* __restrict__ C, __half* __restrict__ Chi,
    __half* __restrict__ Clo, int M, int N, int K) {
    extern __shared__ char sm[];
    const uint32_t sbase = smem_u32_of(sm);

    const int tid  = threadIdx.x;
    const int wid  = tid >> 5;
    const int lane = tid & 31;
    const int m0 = blockIdx.y * 128;
    const int n0 = blockIdx.x * 128;
    const int wm = wid >> 2;
    const int wn = wid & 3;

    // Loader: thread -> (row = tid>>1, two 16B chunks)
    const int lrow = tid >> 1;
    const int lc0  = (tid & 1) * 2;
    const __half* gAh = Ahi + (size_t)(m0 + lrow) * K;
    const __half* gAl = Alo + (size_t)(m0 + lrow) * K;
    const __half* gBh = Bhi + (size_t)(n0 + lrow) * K;

    float acc[4][4][4] = {};
    const int NCH = K / KC;

    auto load_stage = [&](int c, int s) {
        const uint32_t st = sbase + (uint32_t)s * STAGE2_B;
        #pragma unroll
        for (int j = 0; j < 2; j++) {
            const uint32_t c4 = (uint32_t)(lc0 + j);
            const uint32_t dof = gsw((uint32_t)lrow, c4);
            const size_t go = (size_t)c * KC + c4 * 8;
            CPA16(st + dof,               gAh + go);
            CPA16(st + TILE2_B + dof,     gAl + go);
            CPA16(st + 2 * TILE2_B + dof, gBh + go);
        }
    };

    load_stage(0, 0);
    CPA_COMMIT();
    load_stage(1, 1);
    CPA_COMMIT();

    const int arow = wm * 64 + (lane & 15);
    const uint32_t ac4b = (uint32_t)(lane >> 4);
    const int brow = wn * 32 + (lane & 7) + ((lane >> 4) << 3);
    const uint32_t bc4b = (uint32_t)((lane >> 3) & 1);

    for (int c = 0; c < NCH; c++) {
        if (c + 1 < NCH) CPA_WAIT1(); else CPA_WAIT0();
        __syncthreads();
        if (c + 2 < NCH) {
            load_stage(c + 2, (c + 2) % 3);
            CPA_COMMIT();
        }

        const uint32_t Ah_b = sbase + (uint32_t)(c % 3) * STAGE2_B;
        const uint32_t Al_b = Ah_b + TILE2_B;
        const uint32_t Bh_b = Ah_b + 2 * TILE2_B;

        #pragma unroll
        for (int ks = 0; ks < 2; ks++) {
            const uint32_t ac4 = (uint32_t)(ks * 2) + ac4b;
            const uint32_t bc4 = (uint32_t)(ks * 2) + bc4b;
            uint32_t bh[2][4];
            #pragma unroll
            for (int nj2 = 0; nj2 < 2; nj2++)
                ldsm4(bh[nj2], Bh_b + gsw((uint32_t)(brow + nj2 * 16), bc4));
            uint32_t ah[4][4], al[4][4];
            #pragma unroll
            for (int mi = 0; mi < 4; mi++) {
                const uint32_t aoff = gsw((uint32_t)(arow + mi * 16), ac4);
                ldsm4(ah[mi], Ah_b + aoff);
                ldsm4(al[mi], Al_b + aoff);
            }
            #pragma unroll
            for (int nj2 = 0; nj2 < 2; nj2++) {
                #pragma unroll
                for (int mi = 0; mi < 4; mi++) {
                    #pragma unroll
                    for (int j = 0; j < 2; j++) {
                        float* a4 = acc[mi][nj2 * 2 + j];
                        mma_f16(a4, ah[mi], &bh[nj2][2 * j]);
                        mma_f16(a4, al[mi], &bh[nj2][2 * j]);
                    }
                }
            }
        }
    }

    const int gr = lane >> 2;
    const int gc = (lane & 3) * 2;
    #pragma unroll
    for (int mi = 0; mi < 4; mi++) {
        #pragma unroll
        for (int nj = 0; nj < 4; nj++) {
            const int row = m0 + wm * 64 + mi * 16 + gr;
            const int col = n0 + wn * 32 + nj * 8 + gc;
            if (SPLIT) {
                *(uint32_t*)&Chi[(size_t)row * N + col] = pack2h(acc[mi][nj][0], acc[mi][nj][1]);
                *(uint32_t*)&Clo[(size_t)row * N + col] = pack2h_lo(acc[mi][nj][0], acc[mi][nj][1]);
                *(uint32_t*)&Chi[(size_t)(row + 8) * N + col] = pack2h(acc[mi][nj][2], acc[mi][nj][3]);
                *(uint32_t*)&Clo[(size_t)(row + 8) * N + col] = pack2h_lo(acc[mi][nj][2], acc[mi][nj][3]);
            } else {
                *(float2*)&C[(size_t)row * N + col] =
                    make_float2(acc[mi][nj][0], acc[mi][nj][1]);
                *(float2*)&C[(size_t)(row + 8) * N + col] =
                    make_float2(acc[mi][nj][2], acc[mi][nj][3]);
            }
        }
    }
}

// ---------------------------------------------------------------------------
// Tensor-core causal flash attention (fp16x2).
// Q and P kept hi+lo (22-bit); K, V fp16-rounded. One CTA = 128-row q-tile,
// 8 warps, k-tiles of 64, double-buffered K/V, one __syncthreads per tile.
// ---------------------------------------------------------------------------
#define FA_STR 144                  // bytes per smem row (64 fp16 + 8 pad)
#define FA_QT  (128 * FA_STR)       // 18432 (Q tile: 128 rows)
#define FA_KT  (64 * FA_STR)        // 9216  (K/V tile: 64 rows)
#define FA_SMEM (2 * FA_QT + 2 * 2 * FA_KT)   // 73728

__global__ __launch_bounds__(256) void flash_tc(
    const __half* __restrict__ qkh, const __half* __restrict__ qkl,
    __half* __restrict__ oh, __half* __restrict__ ol) {
    extern __shared__ char sm[];
    const uint32_t sb = smem_u32_of(sm);
    const int qt = (int)gridDim.x - 1 - (int)blockIdx.x;   // long tiles first
    const int h  = blockIdx.y;
    const int b  = blockIdx.z;
    const int tid = threadIdx.x;
    const int w = tid >> 5;
    const int l = tid & 31;

    // Q load: 128 rows (hi + lo), thread -> (row = tid>>1, 64B half)
    {
        const int r  = tid >> 1;
        const int hf = tid & 1;
        const size_t qoff = ((size_t)(b * TT + qt * 128 + r)) * QKV_COLS + h * HD + hf * 32;
        const uint32_t d0 = sb + (uint32_t)r * FA_STR + (uint32_t)hf * 64;
        #pragma unroll
        for (int i = 0; i < 4; i++) {
            CPA16(d0 + 16 * i,         qkh + qoff + 8 * i);
            CPA16(d0 + FA_QT + 16 * i, qkl + qoff + 8 * i);
        }
    }

    // K/V load (hi only): 64 rows, thread -> (row = tid>>2, 32B quarter)
    const int kr = tid >> 2;
    const int kq = tid & 3;
    auto load_kv = [&](int kt, int s) {
        const size_t koff = ((size_t)(b * TT + kt * 64 + kr)) * QKV_COLS + HH + h * HD + kq * 16;
        const size_t voff = koff + HH;
        const uint32_t d = sb + 2 * FA_QT + (uint32_t)s * 2 * FA_KT
                         + (uint32_t)kr * FA_STR + (uint32_t)kq * 32;
        CPA16(d,              qkh + koff);
        CPA16(d + 16,         qkh + koff + 8);
        CPA16(d + FA_KT,      qkh + voff);
        CPA16(d + FA_KT + 16, qkh + voff + 8);
    };

    load_kv(0, 0);
    CPA_COMMIT();

    float o[8][4] = {};
    float m0 = -1e30f, m1 = -1e30f, l0 = 0.0f, l1 = 0.0f;
    uint32_t qfh[4][4], qfl[4][4];
    const int nkt = 2 * qt + 2;
    const float SCL = 0.18033688011112042f;    // (1/8) * log2(e)

    const uint32_t qa = sb + (uint32_t)(w * 16 + (l & 15)) * FA_STR + (uint32_t)((l >> 4) * 8) * 2;
    const uint32_t kb_row = (uint32_t)((l & 7) + ((l >> 4) << 3)) * FA_STR
                          + (uint32_t)(((l >> 3) & 1) * 8) * 2;
    const uint32_t vb_row = (uint32_t)((l & 7) + (((l >> 3) & 1) << 3)) * FA_STR
                          + (uint32_t)((l >> 4) * 8) * 2;

    const int grow0 = qt * 128 + w * 16 + (l >> 2);   // global q row (first)
    const int cb    = (l & 3) * 2;

    for (int kt = 0; kt < nkt; kt++) {
        const int s = kt & 1;
        CPA_WAIT0();
        __syncthreads();
        if (kt + 1 < nkt) {
            load_kv(kt + 1, s ^ 1);
            CPA_COMMIT();
        }

        if (kt == 0) {
            #pragma unroll
            for (int ks = 0; ks < 4; ks++) {
                ldsm4(qfh[ks], qa + ks * 32);
                ldsm4(qfl[ks], qa + FA_QT + ks * 32);
            }
        }

        const uint32_t Kb = sb + 2 * FA_QT + (uint32_t)s * 2 * FA_KT;
        const uint32_t Vb = Kb + FA_KT;

        // S = (Qhi+Qlo) Kh^T (fp16x2)
        float sc[8][4] = {};
        #pragma unroll
        for (int g = 0; g < 4; g++) {
            #pragma unroll
            for (int ks = 0; ks < 4; ks++) {
                uint32_t bh[4];
                ldsm4(bh, Kb + (uint32_t)(g * 16) * FA_STR + kb_row + ks * 32);
                mma_f16(sc[2 * g],     qfh[ks], &bh[0]);
                mma_f16(sc[2 * g],     qfl[ks], &bh[0]);
                mma_f16(sc[2 * g + 1], qfh[ks], &bh[2]);
                mma_f16(sc[2 * g + 1], qfl[ks], &bh[2]);
            }
        }

        // scale + causal mask (tiles at/after the diagonal band)
        const bool diag = (kt >= 2 * qt);
        float mx0 = -1e30f, mx1 = -1e30f;
        #pragma unroll
        for (int j = 0; j < 8; j++) {
            float s0 = sc[j][0] * SCL, s1 = sc[j][1] * SCL;
            float s2 = sc[j][2] * SCL, s3 = sc[j][3] * SCL;
            if (diag) {
                const int c = kt * 64 + j * 8 + cb;
                if (c     > grow0)     s0 = -1e30f;
                if (c + 1 > grow0)     s1 = -1e30f;
                if (c     > grow0 + 8) s2 = -1e30f;
                if (c + 1 > grow0 + 8) s3 = -1e30f;
            }
            sc[j][0] = s0; sc[j][1] = s1; sc[j][2] = s2; sc[j][3] = s3;
            mx0 = fmaxf(mx0, fmaxf(s0, s1));
            mx1 = fmaxf(mx1, fmaxf(s2, s3));
        }
        mx0 = fmaxf(mx0, __shfl_xor_sync(0xffffffffu, mx0, 1));
        mx0 = fmaxf(mx0, __shfl_xor_sync(0xffffffffu, mx0, 2));
        mx1 = fmaxf(mx1, __shfl_xor_sync(0xffffffffu, mx1, 1));
        mx1 = fmaxf(mx1, __shfl_xor_sync(0xffffffffu, mx1, 2));

        const float mn0 = fmaxf(m0, mx0);
        const float mn1 = fmaxf(m1, mx1);
        const float corr0 = ex2f(m0 - mn0);
        const float corr1 = ex2f(m1 - mn1);
        float sum0 = 0.0f, sum1 = 0.0f;
        #pragma unroll
        for (int j = 0; j < 8; j++) {
            sc[j][0] = ex2f(sc[j][0] - mn0); sum0 += sc[j][0];
            sc[j][1] = ex2f(sc[j][1] - mn0); sum0 += sc[j][1];
            sc[j][2] = ex2f(sc[j][2] - mn1); sum1 += sc[j][2];
            sc[j][3] = ex2f(sc[j][3] - mn1); sum1 += sc[j][3];
        }
        sum0 += __shfl_xor_sync(0xffffffffu, sum0, 1);
        sum0 += __shfl_xor_sync(0xffffffffu, sum0, 2);
        sum1 += __shfl_xor_sync(0xffffffffu, sum1, 1);
        sum1 += __shfl_xor_sync(0xffffffffu, sum1, 2);
        l0 = l0 * corr0 + sum0;
        l1 = l1 * corr1 + sum1;
        m0 = mn0; m1 = mn1;

        #pragma unroll
        for (int j = 0; j < 8; j++) {
            o[j][0] *= corr0; o[j][1] *= corr0;
            o[j][2] *= corr1; o[j][3] *= corr1;
        }

        // P fragments (hi/lo fp16) from S accumulators
        uint32_t pah[4][4], pal[4][4];
        #pragma unroll
        for (int ks = 0; ks < 4; ks++) {
            pah[ks][0] = pack2h(sc[2 * ks][0],        sc[2 * ks][1]);
            pal[ks][0] = pack2h_lo(sc[2 * ks][0],     sc[2 * ks][1]);
            pah[ks][1] = pack2h(sc[2 * ks][2],        sc[2 * ks][3]);
            pal[ks][1] = pack2h_lo(sc[2 * ks][2],     sc[2 * ks][3]);
            pah[ks][2] = pack2h(sc[2 * ks + 1][0],    sc[2 * ks + 1][1]);
            pal[ks][2] = pack2h_lo(sc[2 * ks + 1][0], sc[2 * ks + 1][1]);
            pah[ks][3] = pack2h(sc[2 * ks + 1][2],    sc[2 * ks + 1][3]);
            pal[ks][3] = pack2h_lo(sc[2 * ks + 1][2], sc[2 * ks + 1][3]);
        }

        // O += (Phi+Plo) Vh (fp16x2), V via ldmatrix.trans
        #pragma unroll
        for (int g = 0; g < 4; g++) {
            #pragma unroll
            for (int ks = 0; ks < 4; ks++) {
                uint32_t vh[4];
                ldsm4t(vh, Vb + (uint32_t)(ks * 16) * FA_STR + vb_row + g * 32);
                mma_f16(o[2 * g],     pah[ks], &vh[0]);
                mma_f16(o[2 * g],     pal[ks], &vh[0]);
                mma_f16(o[2 * g + 1], pah[ks], &vh[2]);
                mma_f16(o[2 * g + 1], pal[ks], &vh[2]);
            }
        }
    }

    // Epilogue: normalize + write hi/lo fp16
    const float i0 = 1.0f / l0;
    const float i1 = 1.0f / l1;
    const size_t row0 = (size_t)(b * TT + qt * 128 + w * 16 + (l >> 2));
    const size_t row1 = row0 + 8;
    const int colb = h * HD + cb;
    #pragma unroll
    for (int j = 0; j < 8; j++) {
        const size_t c = colb + j * 8;
        const float v0 = o[j][0] * i0, v1 = o[j][1] * i0;
        const float v2 = o[j][2] * i1, v3 = o[j][3] * i1;
        *(uint32_t*)&oh[row0 * HH + c] = pack2h(v0, v1);
        *(uint32_t*)&ol[row0 * HH + c] = pack2h_lo(v0, v1);
        *(uint32_t*)&oh[row1 * HH + c] = pack2h(v2, v3);
        *(uint32_t*)&ol[row1 * HH + c] = pack2h_lo(v2, v3);
    }
}

// ---------------------------------------------------------------------------
extern "C" void kernel_launch(void* const* d_in, const int* in_sizes, int n_in,
                              void* d_out, int out_size) {
    const float* x    = (const float*)d_in[0];   // [4,2048,1024]
    const float* Wqkv = (const float*)d_in[1];   // [3072,1024]
    const float* Wout = (const float*)d_in[2];   // [1024,1024]
    float* out = (float*)d_out;                  // [4,2048,1024]

    __half *qh, *ql, *xhi, *xlo, *wqh, *woh, *ahi, *alo;
    cudaGetSymbolAddress((void**)&qh,  g_qkv_hi);
    cudaGetSymbolAddress((void**)&ql,  g_qkv_lo);
    cudaGetSymbolAddress((void**)&xhi, g_x_hi);
    cudaGetSymbolAddress((void**)&xlo, g_x_lo);
    cudaGetSymbolAddress((void**)&wqh, g_wqkv_hi);
    cudaGetSymbolAddress((void**)&woh, g_wout_hi);
    cudaGetSymbolAddress((void**)&ahi, g_attn_hi);
    cudaGetSymbolAddress((void**)&alo, g_attn_lo);

    cudaFuncSetAttribute(gemm_hmma<true>,  cudaFuncAttributeMaxDynamicSharedMemorySize, GSMEM);
    cudaFuncSetAttribute(gemm_hmma<false>, cudaFuncAttributeMaxDynamicSharedMemorySize, GSMEM);
    cudaFuncSetAttribute(flash_tc, cudaFuncAttributeMaxDynamicSharedMemorySize, FA_SMEM);

    // Splits/converts
    {
        int n1 = ROWS * HH;
        split_f16<<<(n1 / 4 + 255) / 256, 256>>>(x, xhi, xlo, n1);
        int n2 = QKV_COLS * HH;
        conv_f16<<<(n2 / 4 + 255) / 256, 256>>>(Wqkv, wqh, n2);
        int n3 = HH * HH;
        conv_f16<<<(n3 / 4 + 255) / 256, 256>>>(Wout, woh, n3);
    }

    // 1) qkv = x @ W_qkv^T -> fp16 hi/lo directly
    gemm_hmma<true><<<dim3(QKV_COLS / 128, ROWS / 128), 256, GSMEM>>>(
        xhi, xlo, wqh, nullptr, qh, ql, ROWS, QKV_COLS, HH);

    // 2) tensor-core causal flash attention (128-row q-tiles) -> fp16 hi/lo
    flash_tc<<<dim3(TT / 128, NH, BB), 256, FA_SMEM>>>(qh, ql, ahi, alo);

    // 3) out = attn @ W_out^T -> fp32
    gemm_hmma<false><<<dim3(HH / 128, ROWS / 128), 256, GSMEM>>>(
        ahi, alo, woh, out, nullptr, nullptr, ROWS, HH, HH);
}